// round 11
// baseline (speedup 1.0000x reference)
#include <cuda_runtime.h>
#include <cuda_bf16.h>
#include <cstdint>

#define Bb 8
#define Ff 16
#define Pp 196
#define Dd 768
#define Hh 12
#define HD 64
#define NTOK (Bb*Ff*Pp)          // 25088
#define QKVW (3*Dd)              // 2304
#define GK 768                   // K for all GEMMs
#define KCHUNKS (GK/32)          // 24

// ---------------- scratch (allocation-free: __device__ globals) ----------------
__device__ float         g_qkv[(size_t)NTOK * QKVW];   // 231 MB (f32: attention input)
__device__ float         g_y[(size_t)NTOK * Dd];       // 77 MB
__device__ float         g_x1[(size_t)NTOK * Dd];      // 77 MB
__device__ __nv_bfloat16 g_xb[(size_t)NTOK * Dd];      // 38.5 MB (bf16 GEMM operands)
__device__ __nv_bfloat16 g_x1b[(size_t)NTOK * Dd];     // 38.5 MB
__device__ __nv_bfloat16 g_attnb[(size_t)NTOK * Dd];   // 38.5 MB
__device__ __nv_bfloat16 g_wtb[(size_t)Dd * QKVW];     // 3.5 MB (transposed bf16 weight)

__device__ __forceinline__ void mma_bf16(float* c, const uint32_t* a, const uint32_t* b) {
    asm volatile(
        "mma.sync.aligned.m16n8k16.row.col.f32.bf16.bf16.f32 "
        "{%0,%1,%2,%3}, {%4,%5,%6,%7}, {%8,%9}, {%0,%1,%2,%3};"
        : "+f"(c[0]), "+f"(c[1]), "+f"(c[2]), "+f"(c[3])
        : "r"(a[0]), "r"(a[1]), "r"(a[2]), "r"(a[3]), "r"(b[0]), "r"(b[1]));
}
__device__ __forceinline__ void ldsm_x4(uint32_t* r, uint32_t addr) {
    asm volatile("ldmatrix.sync.aligned.m8n8.x4.shared.b16 {%0,%1,%2,%3}, [%4];"
        : "=r"(r[0]), "=r"(r[1]), "=r"(r[2]), "=r"(r[3]) : "r"(addr));
}
__device__ __forceinline__ uint32_t smem_u32(const void* p) {
    uint32_t a;
    asm("{ .reg .u64 t; cvta.to.shared.u64 t, %1; cvt.u32.u64 %0, t; }" : "=r"(a) : "l"(p));
    return a;
}
__device__ __forceinline__ void cp16(uint32_t dst, const void* src) {
    asm volatile("cp.async.cg.shared.global [%0], [%1], 16;" :: "r"(dst), "l"(src));
}
#define CP_COMMIT() asm volatile("cp.async.commit_group;" ::: "memory")
#define CP_WAIT1()  asm volatile("cp.async.wait_group 1;" ::: "memory")

__device__ __forceinline__ uint32_t packbf(float lo, float hi) {
    __nv_bfloat162 p = __float22bfloat162_rn(make_float2(lo, hi));
    return *reinterpret_cast<uint32_t*>(&p);
}

// ---------------- f32 -> bf16 convert ----------------
__global__ __launch_bounds__(256) void f2b_kernel(
    const float* __restrict__ in, __nv_bfloat16* __restrict__ out, int n4)
{
    int i = blockIdx.x * 256 + threadIdx.x;
    if (i < n4) {
        float4 v = *(const float4*)(in + (size_t)i * 4);
        uint2 u;
        u.x = packbf(v.x, v.y);
        u.y = packbf(v.z, v.w);
        *(uint2*)(out + (size_t)i * 4) = u;
    }
}

// ---------------- weight transpose to bf16: out[N,K] = bf16(in[K,N]) ----------
__global__ __launch_bounds__(256) void transpose_b(
    const float* __restrict__ in, __nv_bfloat16* __restrict__ out, int K, int N)
{
    __shared__ float t[32][33];
    int n0 = blockIdx.x * 32, k0 = blockIdx.y * 32;
    int tx = threadIdx.x, ty = threadIdx.y;   // 32 x 8
#pragma unroll
    for (int j = 0; j < 32; j += 8)
        t[ty + j][tx] = in[(size_t)(k0 + ty + j) * N + n0 + tx];
    __syncthreads();
#pragma unroll
    for (int j = 0; j < 32; j += 8)
        out[(size_t)(n0 + ty + j) * K + k0 + tx] = __float2bfloat16(t[tx][ty + j]);
}

// ---------------- BF16 mma.sync GEMM, cp.async + ldmatrix, 64x64 warp tile ---
// 128x128 CTA tile, BK=32, 128 threads (4 warps 2x2, warp tile 64x64).
// One __syncthreads per K-iter; cp.async overlaps the MMA block.
#define ROWP32 20
#define STAGE_U (128 * ROWP32)
#define NSTG 3
__global__ __launch_bounds__(128) void gemm_mma(
    const __nv_bfloat16* __restrict__ A, const __nv_bfloat16* __restrict__ Bt,
    const float* __restrict__ bias, float* __restrict__ C, int N)
{
    __shared__ __align__(16) uint32_t As[NSTG][STAGE_U];
    __shared__ __align__(16) uint32_t Bs[NSTG][STAGE_U];

    int tid = threadIdx.x;
    int wid = tid >> 5, lane = tid & 31;
    int wr = wid >> 1, wc = wid & 1;          // warp 2x2
    int lg = lane >> 2, lk = lane & 3;
    int bm = blockIdx.y * 128, bn = blockIdx.x * 128;

    // gmem load mapping: each thread owns one row (0..127), 32 bf16 = 4 x cp16
    const __nv_bfloat16* Ag = A  + (size_t)(bm + tid) * GK;
    const __nv_bfloat16* Bg = Bt + (size_t)(bn + tid) * GK;

    uint32_t sAs = smem_u32(&As[0][0]);
    uint32_t sBs = smem_u32(&Bs[0][0]);
    uint32_t soff = (uint32_t)tid * 80;       // row pitch 80 B

    // ldmatrix lane-address offsets (bytes, within a stage)
    uint32_t a_off = (uint32_t)((wr * 64 + (lane & 15)) * 80 + ((lane >> 4) & 1) * 16);
    uint32_t b_off = (uint32_t)((wc * 64 + (lane & 7) + ((lane >> 4) & 1) * 8) * 80
                                + ((lane >> 3) & 1) * 16);

    float acc[4][8][4];
#pragma unroll
    for (int i = 0; i < 4; i++)
#pragma unroll
        for (int j = 0; j < 8; j++)
#pragma unroll
            for (int k = 0; k < 4; k++) acc[i][j][k] = 0.f;

    // prologue: stages 0 and 1
#pragma unroll
    for (int s = 0; s < 2; s++) {
        int kc = s * 32;
        uint32_t ab = sAs + s * (STAGE_U * 4) + soff;
        uint32_t bb = sBs + s * (STAGE_U * 4) + soff;
#pragma unroll
        for (int o = 0; o < 4; o++) {
            cp16(ab + o * 16, Ag + kc + o * 8);
            cp16(bb + o * 16, Bg + kc + o * 8);
        }
        CP_COMMIT();
    }

    for (int it = 0; it < KCHUNKS; it++) {
        CP_WAIT1();
        __syncthreads();
        // prefetch stage it+2 (overwrites stage consumed at it-1; safe after barrier)
        if (it + 2 < KCHUNKS) {
            int s = (it + 2) % NSTG;
            int kc = (it + 2) * 32;
            uint32_t ab = sAs + s * (STAGE_U * 4) + soff;
            uint32_t bb = sBs + s * (STAGE_U * 4) + soff;
#pragma unroll
            for (int o = 0; o < 4; o++) {
                cp16(ab + o * 16, Ag + kc + o * 8);
                cp16(bb + o * 16, Bg + kc + o * 8);
            }
        }
        CP_COMMIT();   // keep group count in lockstep even when empty

        uint32_t aS = sAs + (it % NSTG) * (STAGE_U * 4) + a_off;
        uint32_t bS = sBs + (it % NSTG) * (STAGE_U * 4) + b_off;
#pragma unroll
        for (int ks = 0; ks < 2; ks++) {
            uint32_t af[4][4], bf[8][2];
#pragma unroll
            for (int mt = 0; mt < 4; mt++)
                ldsm_x4(af[mt], aS + mt * (16 * 80) + ks * 32);
#pragma unroll
            for (int j = 0; j < 4; j++)
                ldsm_x4(&bf[2 * j][0], bS + j * (16 * 80) + ks * 32);
#pragma unroll
            for (int mt = 0; mt < 4; mt++)
#pragma unroll
                for (int nt = 0; nt < 8; nt++)
                    mma_bf16(acc[mt][nt], af[mt], bf[nt]);
        }
    }

    // epilogue
#pragma unroll
    for (int mt = 0; mt < 4; mt++) {
        size_t r0 = (size_t)(bm + wr * 64 + mt * 16 + lg);
#pragma unroll
        for (int nt = 0; nt < 8; nt++) {
            int c0 = bn + wc * 64 + nt * 8 + lk * 2;
            float bx = bias[c0], by = bias[c0 + 1];
            float2 v0 = make_float2(acc[mt][nt][0] + bx, acc[mt][nt][1] + by);
            float2 v1 = make_float2(acc[mt][nt][2] + bx, acc[mt][nt][3] + by);
            *(float2*)(C + r0 * N + c0) = v0;
            *(float2*)(C + (r0 + 8) * N + c0) = v1;
        }
    }
}

// ---------------- temporal attention, S=16 ----------------
__global__ __launch_bounds__(256) void attn16_kernel(
    const float* __restrict__ qkv, __nv_bfloat16* __restrict__ out)
{
    __shared__ __align__(16) float Qs[16][68];
    __shared__ __align__(16) float Ks[16][68];
    __shared__ __align__(16) float Vs[16][64];
    __shared__ float Ps[16][17];

    int h = blockIdx.y;
    int seq = blockIdx.x;
    int b = seq / Pp, p = seq % Pp;
    int base = b * Ff * Pp + p;
    int tid = threadIdx.x;

#pragma unroll
    for (int i = 0; i < 4; i++) {
        int idx = i * 256 + tid;
        int f = idx >> 6, d = idx & 63;
        size_t row = (size_t)(base + f * Pp) * QKVW + h * HD + d;
        Qs[f][d] = qkv[row];
        Ks[f][d] = qkv[row + Dd];
        Vs[f][d] = qkv[row + 2 * Dd];
    }
    __syncthreads();

    {
        int q = tid >> 4, k = tid & 15;
        float acc = 0.f;
#pragma unroll
        for (int d4 = 0; d4 < 16; d4++) {
            float4 kv = *(const float4*)(&Ks[k][d4 * 4]);
            float4 qv = *(const float4*)(&Qs[q][d4 * 4]);
            acc += qv.x * kv.x + qv.y * kv.y + qv.z * kv.z + qv.w * kv.w;
        }
        acc *= 0.125f;
        float m = acc;
#pragma unroll
        for (int o = 8; o; o >>= 1) m = fmaxf(m, __shfl_xor_sync(0xffffffffu, m, o));
        float e = __expf(acc - m);
        float s = e;
#pragma unroll
        for (int o = 8; o; o >>= 1) s += __shfl_xor_sync(0xffffffffu, s, o);
        Ps[q][k] = e / s;
    }
    __syncthreads();

    {
        int d = tid & 63;
        int q0 = (tid >> 6) * 4;
        float a0 = 0.f, a1 = 0.f, a2 = 0.f, a3 = 0.f;
#pragma unroll
        for (int k = 0; k < 16; k++) {
            float v = Vs[k][d];
            a0 += Ps[q0 + 0][k] * v;
            a1 += Ps[q0 + 1][k] * v;
            a2 += Ps[q0 + 2][k] * v;
            a3 += Ps[q0 + 3][k] * v;
        }
        size_t o0 = (size_t)(base + (q0 + 0) * Pp) * Dd + h * HD + d;
        out[o0]                       = __float2bfloat16(a0);
        out[o0 + (size_t)Pp * Dd]     = __float2bfloat16(a1);
        out[o0 + (size_t)2 * Pp * Dd] = __float2bfloat16(a2);
        out[o0 + (size_t)3 * Pp * Dd] = __float2bfloat16(a3);
    }
}

// ---------------- spatial attention, S=196 padded to 208, bf16 MMA ----------
#define SPAD 208
#define QRU 36
#define VTR 108
__global__ __launch_bounds__(256) void attn196_kernel(
    const float* __restrict__ qkv, __nv_bfloat16* __restrict__ out)
{
    extern __shared__ __align__(16) uint32_t sm196[];
    uint32_t* Qu = sm196;
    uint32_t* Ku = Qu + SPAD * QRU;
    uint32_t* Vu = Ku + SPAD * QRU;
    uint32_t* Tu = Vu + SPAD * QRU;

    int h = blockIdx.y;
    int base = blockIdx.x * Pp;
    int tid = threadIdx.x;
    int wid = tid >> 5, lane = tid & 31;
    int lg = lane >> 2, lk = lane & 3;

    for (int i = tid; i < SPAD * 32; i += 256) {
        int s = i >> 5, d2 = i & 31;
        uint32_t qv = 0, kv = 0, vv = 0;
        if (s < Pp) {
            const float* row = qkv + (size_t)(base + s) * QKVW + h * HD + d2 * 2;
            float2 q2 = *(const float2*)(row);
            float2 k2 = *(const float2*)(row + Dd);
            float2 v2 = *(const float2*)(row + 2 * Dd);
            qv = packbf(q2.x, q2.y);
            kv = packbf(k2.x, k2.y);
            vv = packbf(v2.x, v2.y);
        }
        Qu[s * QRU + d2] = qv;
        Ku[s * QRU + d2] = kv;
        Vu[s * QRU + d2] = vv;
    }
    __syncthreads();

    {
        const __nv_bfloat16* vb = (const __nv_bfloat16*)Vu;
        for (int i = tid; i < 64 * 104; i += 256) {
            int d = i & 63, s2 = i >> 6;
            uint32_t lo = *(const uint16_t*)(vb + (2 * s2) * (QRU * 2) + d);
            uint32_t hi = *(const uint16_t*)(vb + (2 * s2 + 1) * (QRU * 2) + d);
            Tu[d * VTR + s2] = lo | (hi << 16);
        }
    }
    __syncthreads();

    for (int mt = wid; mt < 13; mt += 8) {
        int r = mt * 16 + lg;

        uint32_t qa[4][4];
#pragma unroll
        for (int kc = 0; kc < 4; kc++) {
            int c2 = kc * 8 + lk;
            qa[kc][0] = Qu[r * QRU + c2];
            qa[kc][1] = Qu[(r + 8) * QRU + c2];
            qa[kc][2] = Qu[r * QRU + c2 + 4];
            qa[kc][3] = Qu[(r + 8) * QRU + c2 + 4];
        }

        float sc[26][4];
#pragma unroll
        for (int nt = 0; nt < 26; nt++)
            sc[nt][0] = sc[nt][1] = sc[nt][2] = sc[nt][3] = 0.f;
#pragma unroll
        for (int nt = 0; nt < 26; nt++) {
            int n = nt * 8 + lg;
#pragma unroll
            for (int kc = 0; kc < 4; kc++) {
                uint32_t b[2];
                b[0] = Ku[n * QRU + kc * 8 + lk];
                b[1] = Ku[n * QRU + kc * 8 + lk + 4];
                mma_bf16(sc[nt], qa[kc], b);
            }
        }

#pragma unroll
        for (int nt = 0; nt < 26; nt++) {
            int col0 = nt * 8 + 2 * lk;
            sc[nt][0] = (col0     < Pp) ? sc[nt][0] * 0.125f : -1e30f;
            sc[nt][1] = (col0 + 1 < Pp) ? sc[nt][1] * 0.125f : -1e30f;
            sc[nt][2] = (col0     < Pp) ? sc[nt][2] * 0.125f : -1e30f;
            sc[nt][3] = (col0 + 1 < Pp) ? sc[nt][3] * 0.125f : -1e30f;
        }

        float m0 = -1e30f, m1 = -1e30f;
#pragma unroll
        for (int nt = 0; nt < 26; nt++) {
            m0 = fmaxf(m0, fmaxf(sc[nt][0], sc[nt][1]));
            m1 = fmaxf(m1, fmaxf(sc[nt][2], sc[nt][3]));
        }
        m0 = fmaxf(m0, __shfl_xor_sync(0xffffffffu, m0, 1));
        m0 = fmaxf(m0, __shfl_xor_sync(0xffffffffu, m0, 2));
        m1 = fmaxf(m1, __shfl_xor_sync(0xffffffffu, m1, 1));
        m1 = fmaxf(m1, __shfl_xor_sync(0xffffffffu, m1, 2));

        float s0 = 0.f, s1 = 0.f;
#pragma unroll
        for (int nt = 0; nt < 26; nt++) {
            sc[nt][0] = __expf(sc[nt][0] - m0); s0 += sc[nt][0];
            sc[nt][1] = __expf(sc[nt][1] - m0); s0 += sc[nt][1];
            sc[nt][2] = __expf(sc[nt][2] - m1); s1 += sc[nt][2];
            sc[nt][3] = __expf(sc[nt][3] - m1); s1 += sc[nt][3];
        }
        s0 += __shfl_xor_sync(0xffffffffu, s0, 1);
        s0 += __shfl_xor_sync(0xffffffffu, s0, 2);
        s1 += __shfl_xor_sync(0xffffffffu, s1, 1);
        s1 += __shfl_xor_sync(0xffffffffu, s1, 2);

        uint32_t pk[13][4];
#pragma unroll
        for (int j = 0; j < 13; j++) {
            pk[j][0] = packbf(sc[2 * j][0],     sc[2 * j][1]);
            pk[j][1] = packbf(sc[2 * j][2],     sc[2 * j][3]);
            pk[j][2] = packbf(sc[2 * j + 1][0], sc[2 * j + 1][1]);
            pk[j][3] = packbf(sc[2 * j + 1][2], sc[2 * j + 1][3]);
        }

        float oa[8][4];
#pragma unroll
        for (int nd = 0; nd < 8; nd++)
            oa[nd][0] = oa[nd][1] = oa[nd][2] = oa[nd][3] = 0.f;
#pragma unroll
        for (int j = 0; j < 13; j++) {
#pragma unroll
            for (int nd = 0; nd < 8; nd++) {
                int n = nd * 8 + lg;
                uint32_t b[2];
                b[0] = Tu[n * VTR + j * 8 + lk];
                b[1] = Tu[n * VTR + j * 8 + lk + 4];
                mma_bf16(oa[nd], pk[j], b);
            }
        }

        float inv0 = 1.0f / s0, inv1 = 1.0f / s1;
        int row0 = r, row1 = r + 8;
#pragma unroll
        for (int nd = 0; nd < 8; nd++) {
            int col = nd * 8 + 2 * lk;
            if (row0 < Pp) {
                uint32_t u = packbf(oa[nd][0] * inv0, oa[nd][1] * inv0);
                *(uint32_t*)(out + (size_t)(base + row0) * Dd + h * HD + col) = u;
            }
            if (row1 < Pp) {
                uint32_t u = packbf(oa[nd][2] * inv1, oa[nd][3] * inv1);
                *(uint32_t*)(out + (size_t)(base + row1) * Dd + h * HD + col) = u;
            }
        }
    }
}

// ---------------- fused residual + LayerNorm (+ optional bf16 copy) ----------
__global__ __launch_bounds__(256) void add_ln_kernel(
    const float* __restrict__ x, const float* __restrict__ y,
    const float* __restrict__ g, const float* __restrict__ b,
    float* __restrict__ out, __nv_bfloat16* __restrict__ outb, int wb)
{
    __shared__ float row_sm[Dd];
    __shared__ float ps[8], ps2[8];
    __shared__ float red[2];

    size_t row = blockIdx.x;
    const float* xr = x + row * Dd;
    const float* yr = y + row * Dd;
    int tid = threadIdx.x;
    int lane = tid & 31, wid = tid >> 5;

    float s = 0.f, s2 = 0.f;
    for (int d = tid; d < Dd; d += 256) {
        float v = xr[d] + yr[d];
        row_sm[d] = v;
        s += v;
        s2 += v * v;
    }
#pragma unroll
    for (int o = 16; o; o >>= 1) {
        s  += __shfl_xor_sync(0xffffffffu, s, o);
        s2 += __shfl_xor_sync(0xffffffffu, s2, o);
    }
    if (lane == 0) { ps[wid] = s; ps2[wid] = s2; }
    __syncthreads();
    if (tid < 8) {
        s = ps[tid]; s2 = ps2[tid];
#pragma unroll
        for (int o = 4; o; o >>= 1) {
            s  += __shfl_xor_sync(0xffu, s, o);
            s2 += __shfl_xor_sync(0xffu, s2, o);
        }
        if (tid == 0) {
            float mean = s / Dd;
            float var = s2 / Dd - mean * mean;
            red[0] = mean;
            red[1] = rsqrtf(var + 1e-5f);
        }
    }
    __syncthreads();
    float mean = red[0], rstd = red[1];
    for (int d = tid; d < Dd; d += 256) {
        float v = (row_sm[d] - mean) * rstd * g[d] + b[d];
        out[row * Dd + d] = v;
        if (wb) outb[row * Dd + d] = __float2bfloat16(v);
    }
}

// ---------------- launch ----------------
extern "C" void kernel_launch(void* const* d_in, const int* in_sizes, int n_in,
                              void* d_out, int out_size)
{
    const float* x      = (const float*)d_in[0];
    const float* Wqkv_t = (const float*)d_in[1];
    const float* bqkv_t = (const float*)d_in[2];
    const float* Wo_t   = (const float*)d_in[3];
    const float* bo_t   = (const float*)d_in[4];
    const float* Wqkv_s = (const float*)d_in[5];
    const float* bqkv_s = (const float*)d_in[6];
    const float* Wo_s   = (const float*)d_in[7];
    const float* bo_s   = (const float*)d_in[8];
    const float* g1     = (const float*)d_in[9];
    const float* b1     = (const float*)d_in[10];
    const float* g2     = (const float*)d_in[11];
    const float* b2     = (const float*)d_in[12];
    float* out = (float*)d_out;

    float *qkv, *y, *x1;
    __nv_bfloat16 *xb, *x1b, *attnb, *wtb;
    cudaGetSymbolAddress((void**)&qkv,   g_qkv);
    cudaGetSymbolAddress((void**)&y,     g_y);
    cudaGetSymbolAddress((void**)&x1,    g_x1);
    cudaGetSymbolAddress((void**)&xb,    g_xb);
    cudaGetSymbolAddress((void**)&x1b,   g_x1b);
    cudaGetSymbolAddress((void**)&attnb, g_attnb);
    cudaGetSymbolAddress((void**)&wtb,   g_wtb);

    const int SMEM196 = (3 * SPAD * QRU + 64 * VTR) * (int)sizeof(uint32_t);  // 117504
    cudaFuncSetAttribute(attn196_kernel, cudaFuncAttributeMaxDynamicSharedMemorySize, SMEM196);

    dim3 tb(32, 8);
    dim3 tg_qkv(QKVW / 32, GK / 32);      // (72, 24)
    dim3 tg_out(Dd / 32, GK / 32);        // (24, 24)
    dim3 gg_qkv(QKVW / 128, NTOK / 128);  // (18, 196)
    dim3 gg_out(Dd / 128, NTOK / 128);    // (6, 196)
    int n4 = NTOK * Dd / 4;

    // x -> bf16
    f2b_kernel<<<(n4 + 255) / 256, 256>>>(x, xb, n4);
    // temporal QKV projection
    transpose_b<<<tg_qkv, tb>>>(Wqkv_t, wtb, GK, QKVW);
    gemm_mma<<<gg_qkv, 128>>>(xb, wtb, bqkv_t, qkv, QKVW);
    // temporal attention (S=16)
    attn16_kernel<<<dim3(Bb * Pp, Hh), 256>>>(qkv, attnb);
    // temporal out-projection
    transpose_b<<<tg_out, tb>>>(Wo_t, wtb, GK, Dd);
    gemm_mma<<<gg_out, 128>>>(attnb, wtb, bo_t, y, Dd);
    // x1 = LN(x + y)  (+ bf16 copy)
    add_ln_kernel<<<NTOK, 256>>>(x, y, g1, b1, x1, x1b, 1);
    // spatial QKV projection
    transpose_b<<<tg_qkv, tb>>>(Wqkv_s, wtb, GK, QKVW);
    gemm_mma<<<gg_qkv, 128>>>(x1b, wtb, bqkv_s, qkv, QKVW);
    // spatial attention (S=196), bf16 MMA flash-style
    attn196_kernel<<<dim3(Bb * Ff, Hh), 256, SMEM196>>>(qkv, attnb);
    // spatial out-projection
    transpose_b<<<tg_out, tb>>>(Wo_s, wtb, GK, Dd);
    gemm_mma<<<gg_out, 128>>>(attnb, wtb, bo_s, y, Dd);
    // out = LN(x1 + y)
    add_ln_kernel<<<NTOK, 256>>>(x1, y, g2, b2, out, (__nv_bfloat16*)nullptr, 0);
}

// round 12
// speedup vs baseline: 1.2589x; 1.2589x over previous
#include <cuda_runtime.h>
#include <cuda_bf16.h>
#include <cstdint>

#define Bb 8
#define Ff 16
#define Pp 196
#define Dd 768
#define Hh 12
#define HD 64
#define NTOK (Bb*Ff*Pp)          // 25088
#define QKVW (3*Dd)              // 2304
#define GK 768                   // K for all GEMMs
#define KCHUNKS (GK/32)          // 24

// ---------------- scratch (allocation-free: __device__ globals) ----------------
__device__ float         g_qkv[(size_t)NTOK * QKVW];   // 231 MB (f32: attention input)
__device__ float         g_y[(size_t)NTOK * Dd];       // 77 MB
__device__ float         g_x1[(size_t)NTOK * Dd];      // 77 MB
__device__ __nv_bfloat16 g_xb[(size_t)NTOK * Dd];      // 38.5 MB (bf16 GEMM operands)
__device__ __nv_bfloat16 g_x1b[(size_t)NTOK * Dd];     // 38.5 MB
__device__ __nv_bfloat16 g_attnb[(size_t)NTOK * Dd];   // 38.5 MB
__device__ __nv_bfloat16 g_wtb[(size_t)Dd * QKVW];     // 3.5 MB (transposed bf16 weight)

__device__ __forceinline__ void mma_bf16(float* c, const uint32_t* a, const uint32_t* b) {
    asm volatile(
        "mma.sync.aligned.m16n8k16.row.col.f32.bf16.bf16.f32 "
        "{%0,%1,%2,%3}, {%4,%5,%6,%7}, {%8,%9}, {%0,%1,%2,%3};"
        : "+f"(c[0]), "+f"(c[1]), "+f"(c[2]), "+f"(c[3])
        : "r"(a[0]), "r"(a[1]), "r"(a[2]), "r"(a[3]), "r"(b[0]), "r"(b[1]));
}
__device__ __forceinline__ void ldsm_x4(uint32_t* r, uint32_t addr) {
    asm volatile("ldmatrix.sync.aligned.m8n8.x4.shared.b16 {%0,%1,%2,%3}, [%4];"
        : "=r"(r[0]), "=r"(r[1]), "=r"(r[2]), "=r"(r[3]) : "r"(addr));
}
__device__ __forceinline__ uint32_t smem_u32(const void* p) {
    uint32_t a;
    asm("{ .reg .u64 t; cvta.to.shared.u64 t, %1; cvt.u32.u64 %0, t; }" : "=r"(a) : "l"(p));
    return a;
}
__device__ __forceinline__ void cp16(uint32_t dst, const void* src) {
    asm volatile("cp.async.cg.shared.global [%0], [%1], 16;" :: "r"(dst), "l"(src));
}
#define CP_COMMIT() asm volatile("cp.async.commit_group;" ::: "memory")
#define CP_WAIT1()  asm volatile("cp.async.wait_group 1;" ::: "memory")

__device__ __forceinline__ uint32_t packbf(float lo, float hi) {
    __nv_bfloat162 p = __float22bfloat162_rn(make_float2(lo, hi));
    return *reinterpret_cast<uint32_t*>(&p);
}

// ---------------- f32 -> bf16 convert ----------------
__global__ __launch_bounds__(256) void f2b_kernel(
    const float* __restrict__ in, __nv_bfloat16* __restrict__ out, int n4)
{
    int i = blockIdx.x * 256 + threadIdx.x;
    if (i < n4) {
        float4 v = *(const float4*)(in + (size_t)i * 4);
        uint2 u;
        u.x = packbf(v.x, v.y);
        u.y = packbf(v.z, v.w);
        *(uint2*)(out + (size_t)i * 4) = u;
    }
}

// ---------------- weight transpose to bf16: out[N,K] = bf16(in[K,N]) ----------
__global__ __launch_bounds__(256) void transpose_b(
    const float* __restrict__ in, __nv_bfloat16* __restrict__ out, int K, int N)
{
    __shared__ float t[32][33];
    int n0 = blockIdx.x * 32, k0 = blockIdx.y * 32;
    int tx = threadIdx.x, ty = threadIdx.y;   // 32 x 8
#pragma unroll
    for (int j = 0; j < 32; j += 8)
        t[ty + j][tx] = in[(size_t)(k0 + ty + j) * N + n0 + tx];
    __syncthreads();
#pragma unroll
    for (int j = 0; j < 32; j += 8)
        out[(size_t)(n0 + ty + j) * K + k0 + tx] = __float2bfloat16(t[tx][ty + j]);
}

// ---------------- BF16 mma.sync GEMM, cp.async + ldmatrix (round-10 config) --
// 128x128 CTA tile, BK=32, 256 threads (8 warps 2x4, warp tile 64x32), 2 CTA/SM.
// ONE __syncthreads per K-iter; cp.async for stage it+2 issued before the MMAs
// (stage (it+2)%3 == (it-1)%3 was fully consumed before this barrier).
#define ROWP32 20
#define STAGE_U (128 * ROWP32)
#define NSTG 3
__global__ __launch_bounds__(256, 2) void gemm_mma(
    const __nv_bfloat16* __restrict__ A, const __nv_bfloat16* __restrict__ Bt,
    const float* __restrict__ bias, float* __restrict__ C, int N)
{
    __shared__ __align__(16) uint32_t As[NSTG][STAGE_U];
    __shared__ __align__(16) uint32_t Bs[NSTG][STAGE_U];

    int tid = threadIdx.x;
    int wid = tid >> 5, lane = tid & 31;
    int wr = wid >> 2, wc = wid & 3;
    int lg = lane >> 2, lk = lane & 3;
    int bm = blockIdx.y * 128, bn = blockIdx.x * 128;

    int ldr = tid >> 1;
    int half = tid & 1;
    int ebase = half * 16;
    int c2base = half * 8;

    const __nv_bfloat16* Ag = A  + (size_t)(bm + ldr) * GK + ebase;
    const __nv_bfloat16* Bg = Bt + (size_t)(bn + ldr) * GK + ebase;

    uint32_t sAs = smem_u32(&As[0][0]);
    uint32_t sBs = smem_u32(&Bs[0][0]);
    uint32_t soff = (uint32_t)(ldr * ROWP32 + c2base) * 4;

    uint32_t a_off = (uint32_t)((wr * 64 + (lane & 15)) * 80 + ((lane >> 4) & 1) * 16);
    uint32_t b_off = (uint32_t)((wc * 32 + (lane & 7) + ((lane >> 4) & 1) * 8) * 80
                                + ((lane >> 3) & 1) * 16);

    float acc[4][4][4];
#pragma unroll
    for (int i = 0; i < 4; i++)
#pragma unroll
        for (int j = 0; j < 4; j++)
#pragma unroll
            for (int k = 0; k < 4; k++) acc[i][j][k] = 0.f;

#pragma unroll
    for (int s = 0; s < 2; s++) {
        int kc = s * 32;
        uint32_t ab = sAs + s * (STAGE_U * 4) + soff;
        uint32_t bb = sBs + s * (STAGE_U * 4) + soff;
        cp16(ab,      Ag + kc);
        cp16(ab + 16, Ag + kc + 8);
        cp16(bb,      Bg + kc);
        cp16(bb + 16, Bg + kc + 8);
        CP_COMMIT();
    }

    for (int it = 0; it < KCHUNKS; it++) {
        CP_WAIT1();
        __syncthreads();
        // prefetch stage it+2 (overwrites stage consumed at it-1; safe post-barrier)
        if (it + 2 < KCHUNKS) {
            int s = (it + 2) % NSTG;
            int kc = (it + 2) * 32;
            uint32_t ab = sAs + s * (STAGE_U * 4) + soff;
            uint32_t bb = sBs + s * (STAGE_U * 4) + soff;
            cp16(ab,      Ag + kc);
            cp16(ab + 16, Ag + kc + 8);
            cp16(bb,      Bg + kc);
            cp16(bb + 16, Bg + kc + 8);
        }
        CP_COMMIT();   // keep group count in lockstep even when empty

        uint32_t aS = sAs + (it % NSTG) * (STAGE_U * 4) + a_off;
        uint32_t bS = sBs + (it % NSTG) * (STAGE_U * 4) + b_off;
#pragma unroll
        for (int ks = 0; ks < 2; ks++) {
            uint32_t af[4][4], bf[4][2];
#pragma unroll
            for (int mt = 0; mt < 4; mt++)
                ldsm_x4(af[mt], aS + mt * (16 * 80) + ks * 32);
#pragma unroll
            for (int j = 0; j < 2; j++)
                ldsm_x4(&bf[2 * j][0], bS + j * (16 * 80) + ks * 32);
#pragma unroll
            for (int mt = 0; mt < 4; mt++)
#pragma unroll
                for (int nt = 0; nt < 4; nt++)
                    mma_bf16(acc[mt][nt], af[mt], bf[nt]);
        }
    }

#pragma unroll
    for (int mt = 0; mt < 4; mt++) {
        size_t r0 = (size_t)(bm + wr * 64 + mt * 16 + lg);
#pragma unroll
        for (int nt = 0; nt < 4; nt++) {
            int c0 = bn + wc * 32 + nt * 8 + lk * 2;
            float bx = bias[c0], by = bias[c0 + 1];
            float2 v0 = make_float2(acc[mt][nt][0] + bx, acc[mt][nt][1] + by);
            float2 v1 = make_float2(acc[mt][nt][2] + bx, acc[mt][nt][3] + by);
            *(float2*)(C + r0 * N + c0) = v0;
            *(float2*)(C + (r0 + 8) * N + c0) = v1;
        }
    }
}

// ---------------- temporal attention, S=16 ----------------
__global__ __launch_bounds__(256) void attn16_kernel(
    const float* __restrict__ qkv, __nv_bfloat16* __restrict__ out)
{
    __shared__ __align__(16) float Qs[16][68];
    __shared__ __align__(16) float Ks[16][68];
    __shared__ __align__(16) float Vs[16][64];
    __shared__ float Ps[16][17];

    int h = blockIdx.y;
    int seq = blockIdx.x;
    int b = seq / Pp, p = seq % Pp;
    int base = b * Ff * Pp + p;
    int tid = threadIdx.x;

#pragma unroll
    for (int i = 0; i < 4; i++) {
        int idx = i * 256 + tid;
        int f = idx >> 6, d = idx & 63;
        size_t row = (size_t)(base + f * Pp) * QKVW + h * HD + d;
        Qs[f][d] = qkv[row];
        Ks[f][d] = qkv[row + Dd];
        Vs[f][d] = qkv[row + 2 * Dd];
    }
    __syncthreads();

    {
        int q = tid >> 4, k = tid & 15;
        float acc = 0.f;
#pragma unroll
        for (int d4 = 0; d4 < 16; d4++) {
            float4 kv = *(const float4*)(&Ks[k][d4 * 4]);
            float4 qv = *(const float4*)(&Qs[q][d4 * 4]);
            acc += qv.x * kv.x + qv.y * kv.y + qv.z * kv.z + qv.w * kv.w;
        }
        acc *= 0.125f;
        float m = acc;
#pragma unroll
        for (int o = 8; o; o >>= 1) m = fmaxf(m, __shfl_xor_sync(0xffffffffu, m, o));
        float e = __expf(acc - m);
        float s = e;
#pragma unroll
        for (int o = 8; o; o >>= 1) s += __shfl_xor_sync(0xffffffffu, s, o);
        Ps[q][k] = e / s;
    }
    __syncthreads();

    {
        int d = tid & 63;
        int q0 = (tid >> 6) * 4;
        float a0 = 0.f, a1 = 0.f, a2 = 0.f, a3 = 0.f;
#pragma unroll
        for (int k = 0; k < 16; k++) {
            float v = Vs[k][d];
            a0 += Ps[q0 + 0][k] * v;
            a1 += Ps[q0 + 1][k] * v;
            a2 += Ps[q0 + 2][k] * v;
            a3 += Ps[q0 + 3][k] * v;
        }
        size_t o0 = (size_t)(base + (q0 + 0) * Pp) * Dd + h * HD + d;
        out[o0]                       = __float2bfloat16(a0);
        out[o0 + (size_t)Pp * Dd]     = __float2bfloat16(a1);
        out[o0 + (size_t)2 * Pp * Dd] = __float2bfloat16(a2);
        out[o0 + (size_t)3 * Pp * Dd] = __float2bfloat16(a3);
    }
}

// ---------------- spatial attention, S=196 padded to 208, bf16 MMA ----------
#define SPAD 208
#define QRU 36
#define VTR 108
__global__ __launch_bounds__(256) void attn196_kernel(
    const float* __restrict__ qkv, __nv_bfloat16* __restrict__ out)
{
    extern __shared__ __align__(16) uint32_t sm196[];
    uint32_t* Qu = sm196;
    uint32_t* Ku = Qu + SPAD * QRU;
    uint32_t* Vu = Ku + SPAD * QRU;
    uint32_t* Tu = Vu + SPAD * QRU;

    int h = blockIdx.y;
    int base = blockIdx.x * Pp;
    int tid = threadIdx.x;
    int wid = tid >> 5, lane = tid & 31;
    int lg = lane >> 2, lk = lane & 3;

    for (int i = tid; i < SPAD * 32; i += 256) {
        int s = i >> 5, d2 = i & 31;
        uint32_t qv = 0, kv = 0, vv = 0;
        if (s < Pp) {
            const float* row = qkv + (size_t)(base + s) * QKVW + h * HD + d2 * 2;
            float2 q2 = *(const float2*)(row);
            float2 k2 = *(const float2*)(row + Dd);
            float2 v2 = *(const float2*)(row + 2 * Dd);
            qv = packbf(q2.x, q2.y);
            kv = packbf(k2.x, k2.y);
            vv = packbf(v2.x, v2.y);
        }
        Qu[s * QRU + d2] = qv;
        Ku[s * QRU + d2] = kv;
        Vu[s * QRU + d2] = vv;
    }
    __syncthreads();

    {
        const __nv_bfloat16* vb = (const __nv_bfloat16*)Vu;
        for (int i = tid; i < 64 * 104; i += 256) {
            int d = i & 63, s2 = i >> 6;
            uint32_t lo = *(const uint16_t*)(vb + (2 * s2) * (QRU * 2) + d);
            uint32_t hi = *(const uint16_t*)(vb + (2 * s2 + 1) * (QRU * 2) + d);
            Tu[d * VTR + s2] = lo | (hi << 16);
        }
    }
    __syncthreads();

    for (int mt = wid; mt < 13; mt += 8) {
        int r = mt * 16 + lg;

        uint32_t qa[4][4];
#pragma unroll
        for (int kc = 0; kc < 4; kc++) {
            int c2 = kc * 8 + lk;
            qa[kc][0] = Qu[r * QRU + c2];
            qa[kc][1] = Qu[(r + 8) * QRU + c2];
            qa[kc][2] = Qu[r * QRU + c2 + 4];
            qa[kc][3] = Qu[(r + 8) * QRU + c2 + 4];
        }

        float sc[26][4];
#pragma unroll
        for (int nt = 0; nt < 26; nt++)
            sc[nt][0] = sc[nt][1] = sc[nt][2] = sc[nt][3] = 0.f;
#pragma unroll
        for (int nt = 0; nt < 26; nt++) {
            int n = nt * 8 + lg;
#pragma unroll
            for (int kc = 0; kc < 4; kc++) {
                uint32_t b[2];
                b[0] = Ku[n * QRU + kc * 8 + lk];
                b[1] = Ku[n * QRU + kc * 8 + lk + 4];
                mma_bf16(sc[nt], qa[kc], b);
            }
        }

#pragma unroll
        for (int nt = 0; nt < 26; nt++) {
            int col0 = nt * 8 + 2 * lk;
            sc[nt][0] = (col0     < Pp) ? sc[nt][0] * 0.125f : -1e30f;
            sc[nt][1] = (col0 + 1 < Pp) ? sc[nt][1] * 0.125f : -1e30f;
            sc[nt][2] = (col0     < Pp) ? sc[nt][2] * 0.125f : -1e30f;
            sc[nt][3] = (col0 + 1 < Pp) ? sc[nt][3] * 0.125f : -1e30f;
        }

        float m0 = -1e30f, m1 = -1e30f;
#pragma unroll
        for (int nt = 0; nt < 26; nt++) {
            m0 = fmaxf(m0, fmaxf(sc[nt][0], sc[nt][1]));
            m1 = fmaxf(m1, fmaxf(sc[nt][2], sc[nt][3]));
        }
        m0 = fmaxf(m0, __shfl_xor_sync(0xffffffffu, m0, 1));
        m0 = fmaxf(m0, __shfl_xor_sync(0xffffffffu, m0, 2));
        m1 = fmaxf(m1, __shfl_xor_sync(0xffffffffu, m1, 1));
        m1 = fmaxf(m1, __shfl_xor_sync(0xffffffffu, m1, 2));

        float s0 = 0.f, s1 = 0.f;
#pragma unroll
        for (int nt = 0; nt < 26; nt++) {
            sc[nt][0] = __expf(sc[nt][0] - m0); s0 += sc[nt][0];
            sc[nt][1] = __expf(sc[nt][1] - m0); s0 += sc[nt][1];
            sc[nt][2] = __expf(sc[nt][2] - m1); s1 += sc[nt][2];
            sc[nt][3] = __expf(sc[nt][3] - m1); s1 += sc[nt][3];
        }
        s0 += __shfl_xor_sync(0xffffffffu, s0, 1);
        s0 += __shfl_xor_sync(0xffffffffu, s0, 2);
        s1 += __shfl_xor_sync(0xffffffffu, s1, 1);
        s1 += __shfl_xor_sync(0xffffffffu, s1, 2);

        uint32_t pk[13][4];
#pragma unroll
        for (int j = 0; j < 13; j++) {
            pk[j][0] = packbf(sc[2 * j][0],     sc[2 * j][1]);
            pk[j][1] = packbf(sc[2 * j][2],     sc[2 * j][3]);
            pk[j][2] = packbf(sc[2 * j + 1][0], sc[2 * j + 1][1]);
            pk[j][3] = packbf(sc[2 * j + 1][2], sc[2 * j + 1][3]);
        }

        float oa[8][4];
#pragma unroll
        for (int nd = 0; nd < 8; nd++)
            oa[nd][0] = oa[nd][1] = oa[nd][2] = oa[nd][3] = 0.f;
#pragma unroll
        for (int j = 0; j < 13; j++) {
#pragma unroll
            for (int nd = 0; nd < 8; nd++) {
                int n = nd * 8 + lg;
                uint32_t b[2];
                b[0] = Tu[n * VTR + j * 8 + lk];
                b[1] = Tu[n * VTR + j * 8 + lk + 4];
                mma_bf16(oa[nd], pk[j], b);
            }
        }

        float inv0 = 1.0f / s0, inv1 = 1.0f / s1;
        int row0 = r, row1 = r + 8;
#pragma unroll
        for (int nd = 0; nd < 8; nd++) {
            int col = nd * 8 + 2 * lk;
            if (row0 < Pp) {
                uint32_t u = packbf(oa[nd][0] * inv0, oa[nd][1] * inv0);
                *(uint32_t*)(out + (size_t)(base + row0) * Dd + h * HD + col) = u;
            }
            if (row1 < Pp) {
                uint32_t u = packbf(oa[nd][2] * inv1, oa[nd][3] * inv1);
                *(uint32_t*)(out + (size_t)(base + row1) * Dd + h * HD + col) = u;
            }
        }
    }
}

// ---------------- fused residual + LayerNorm (+ optional bf16 copy) ----------
__global__ __launch_bounds__(256) void add_ln_kernel(
    const float* __restrict__ x, const float* __restrict__ y,
    const float* __restrict__ g, const float* __restrict__ b,
    float* __restrict__ out, __nv_bfloat16* __restrict__ outb, int wb)
{
    __shared__ float row_sm[Dd];
    __shared__ float ps[8], ps2[8];
    __shared__ float red[2];

    size_t row = blockIdx.x;
    const float* xr = x + row * Dd;
    const float* yr = y + row * Dd;
    int tid = threadIdx.x;
    int lane = tid & 31, wid = tid >> 5;

    float s = 0.f, s2 = 0.f;
    for (int d = tid; d < Dd; d += 256) {
        float v = xr[d] + yr[d];
        row_sm[d] = v;
        s += v;
        s2 += v * v;
    }
#pragma unroll
    for (int o = 16; o; o >>= 1) {
        s  += __shfl_xor_sync(0xffffffffu, s, o);
        s2 += __shfl_xor_sync(0xffffffffu, s2, o);
    }
    if (lane == 0) { ps[wid] = s; ps2[wid] = s2; }
    __syncthreads();
    if (tid < 8) {
        s = ps[tid]; s2 = ps2[tid];
#pragma unroll
        for (int o = 4; o; o >>= 1) {
            s  += __shfl_xor_sync(0xffu, s, o);
            s2 += __shfl_xor_sync(0xffu, s2, o);
        }
        if (tid == 0) {
            float mean = s / Dd;
            float var = s2 / Dd - mean * mean;
            red[0] = mean;
            red[1] = rsqrtf(var + 1e-5f);
        }
    }
    __syncthreads();
    float mean = red[0], rstd = red[1];
    for (int d = tid; d < Dd; d += 256) {
        float v = (row_sm[d] - mean) * rstd * g[d] + b[d];
        out[row * Dd + d] = v;
        if (wb) outb[row * Dd + d] = __float2bfloat16(v);
    }
}

// ---------------- launch ----------------
extern "C" void kernel_launch(void* const* d_in, const int* in_sizes, int n_in,
                              void* d_out, int out_size)
{
    const float* x      = (const float*)d_in[0];
    const float* Wqkv_t = (const float*)d_in[1];
    const float* bqkv_t = (const float*)d_in[2];
    const float* Wo_t   = (const float*)d_in[3];
    const float* bo_t   = (const float*)d_in[4];
    const float* Wqkv_s = (const float*)d_in[5];
    const float* bqkv_s = (const float*)d_in[6];
    const float* Wo_s   = (const float*)d_in[7];
    const float* bo_s   = (const float*)d_in[8];
    const float* g1     = (const float*)d_in[9];
    const float* b1     = (const float*)d_in[10];
    const float* g2     = (const float*)d_in[11];
    const float* b2     = (const float*)d_in[12];
    float* out = (float*)d_out;

    float *qkv, *y, *x1;
    __nv_bfloat16 *xb, *x1b, *attnb, *wtb;
    cudaGetSymbolAddress((void**)&qkv,   g_qkv);
    cudaGetSymbolAddress((void**)&y,     g_y);
    cudaGetSymbolAddress((void**)&x1,    g_x1);
    cudaGetSymbolAddress((void**)&xb,    g_xb);
    cudaGetSymbolAddress((void**)&x1b,   g_x1b);
    cudaGetSymbolAddress((void**)&attnb, g_attnb);
    cudaGetSymbolAddress((void**)&wtb,   g_wtb);

    const int SMEM196 = (3 * SPAD * QRU + 64 * VTR) * (int)sizeof(uint32_t);  // 117504
    cudaFuncSetAttribute(attn196_kernel, cudaFuncAttributeMaxDynamicSharedMemorySize, SMEM196);

    dim3 tb(32, 8);
    dim3 tg_qkv(QKVW / 32, GK / 32);      // (72, 24)
    dim3 tg_out(Dd / 32, GK / 32);        // (24, 24)
    dim3 gg_qkv(QKVW / 128, NTOK / 128);  // (18, 196)
    dim3 gg_out(Dd / 128, NTOK / 128);    // (6, 196)
    int n4 = NTOK * Dd / 4;

    // x -> bf16
    f2b_kernel<<<(n4 + 255) / 256, 256>>>(x, xb, n4);
    // temporal QKV projection
    transpose_b<<<tg_qkv, tb>>>(Wqkv_t, wtb, GK, QKVW);
    gemm_mma<<<gg_qkv, 256>>>(xb, wtb, bqkv_t, qkv, QKVW);
    // temporal attention (S=16)
    attn16_kernel<<<dim3(Bb * Pp, Hh), 256>>>(qkv, attnb);
    // temporal out-projection
    transpose_b<<<tg_out, tb>>>(Wo_t, wtb, GK, Dd);
    gemm_mma<<<gg_out, 256>>>(attnb, wtb, bo_t, y, Dd);
    // x1 = LN(x + y)  (+ bf16 copy)
    add_ln_kernel<<<NTOK, 256>>>(x, y, g1, b1, x1, x1b, 1);
    // spatial QKV projection
    transpose_b<<<tg_qkv, tb>>>(Wqkv_s, wtb, GK, QKVW);
    gemm_mma<<<gg_qkv, 256>>>(x1b, wtb, bqkv_s, qkv, QKVW);
    // spatial attention (S=196), bf16 MMA flash-style
    attn196_kernel<<<dim3(Bb * Ff, Hh), 256, SMEM196>>>(qkv, attnb);
    // spatial out-projection
    transpose_b<<<tg_out, tb>>>(Wo_s, wtb, GK, Dd);
    gemm_mma<<<gg_out, 256>>>(attnb, wtb, bo_s, y, Dd);
    // out = LN(x1 + y)
    add_ln_kernel<<<NTOK, 256>>>(x1, y, g2, b2, out, (__nv_bfloat16*)nullptr, 0);
}

// round 13
// speedup vs baseline: 1.2779x; 1.0151x over previous
#include <cuda_runtime.h>
#include <cuda_bf16.h>
#include <cstdint>

#define Bb 8
#define Ff 16
#define Pp 196
#define Dd 768
#define Hh 12
#define HD 64
#define NTOK (Bb*Ff*Pp)          // 25088
#define QKVW (3*Dd)              // 2304
#define GK 768                   // K for all GEMMs
#define KCHUNKS (GK/32)          // 24

// ---------------- scratch (allocation-free: __device__ globals) ----------------
__device__ float         g_qkv[(size_t)NTOK * QKVW];   // 231 MB (f32: attention input)
__device__ float         g_y[(size_t)NTOK * Dd];       // 77 MB
__device__ float         g_x1[(size_t)NTOK * Dd];      // 77 MB
__device__ __nv_bfloat16 g_xb[(size_t)NTOK * Dd];      // 38.5 MB (bf16 GEMM operands)
__device__ __nv_bfloat16 g_x1b[(size_t)NTOK * Dd];     // 38.5 MB
__device__ __nv_bfloat16 g_attnb[(size_t)NTOK * Dd];   // 38.5 MB
__device__ __nv_bfloat16 g_wtb[(size_t)Dd * QKVW];     // 3.5 MB (transposed bf16 weight)

__device__ __forceinline__ void mma_bf16(float* c, const uint32_t* a, const uint32_t* b) {
    asm volatile(
        "mma.sync.aligned.m16n8k16.row.col.f32.bf16.bf16.f32 "
        "{%0,%1,%2,%3}, {%4,%5,%6,%7}, {%8,%9}, {%0,%1,%2,%3};"
        : "+f"(c[0]), "+f"(c[1]), "+f"(c[2]), "+f"(c[3])
        : "r"(a[0]), "r"(a[1]), "r"(a[2]), "r"(a[3]), "r"(b[0]), "r"(b[1]));
}
__device__ __forceinline__ void ldsm_x4(uint32_t* r, uint32_t addr) {
    asm volatile("ldmatrix.sync.aligned.m8n8.x4.shared.b16 {%0,%1,%2,%3}, [%4];"
        : "=r"(r[0]), "=r"(r[1]), "=r"(r[2]), "=r"(r[3]) : "r"(addr));
}
__device__ __forceinline__ uint32_t smem_u32(const void* p) {
    uint32_t a;
    asm("{ .reg .u64 t; cvta.to.shared.u64 t, %1; cvt.u32.u64 %0, t; }" : "=r"(a) : "l"(p));
    return a;
}
__device__ __forceinline__ void cp16(uint32_t dst, const void* src) {
    asm volatile("cp.async.cg.shared.global [%0], [%1], 16;" :: "r"(dst), "l"(src));
}
#define CP_COMMIT() asm volatile("cp.async.commit_group;" ::: "memory")
#define CP_WAIT1()  asm volatile("cp.async.wait_group 1;" ::: "memory")

__device__ __forceinline__ uint32_t packbf(float lo, float hi) {
    __nv_bfloat162 p = __float22bfloat162_rn(make_float2(lo, hi));
    return *reinterpret_cast<uint32_t*>(&p);
}

// ---------------- f32 -> bf16 convert ----------------
__global__ __launch_bounds__(256) void f2b_kernel(
    const float* __restrict__ in, __nv_bfloat16* __restrict__ out, int n4)
{
    int i = blockIdx.x * 256 + threadIdx.x;
    if (i < n4) {
        float4 v = *(const float4*)(in + (size_t)i * 4);
        uint2 u;
        u.x = packbf(v.x, v.y);
        u.y = packbf(v.z, v.w);
        *(uint2*)(out + (size_t)i * 4) = u;
    }
}

// ---------------- weight transpose to bf16: out[N,K] = bf16(in[K,N]) ----------
__global__ __launch_bounds__(256) void transpose_b(
    const float* __restrict__ in, __nv_bfloat16* __restrict__ out, int K, int N)
{
    __shared__ float t[32][33];
    int n0 = blockIdx.x * 32, k0 = blockIdx.y * 32;
    int tx = threadIdx.x, ty = threadIdx.y;   // 32 x 8
#pragma unroll
    for (int j = 0; j < 32; j += 8)
        t[ty + j][tx] = in[(size_t)(k0 + ty + j) * N + n0 + tx];
    __syncthreads();
#pragma unroll
    for (int j = 0; j < 32; j += 8)
        out[(size_t)(n0 + ty + j) * K + k0 + tx] = __float2bfloat16(t[tx][ty + j]);
}

// ---------------- BF16 mma.sync GEMM, cp.async + ldmatrix -------------------
// 128x128 CTA tile, BK=32, 256 threads (8 warps 2x4, warp tile 64x32), 2 CTA/SM.
// ONE __syncthreads per K-iter.
#define ROWP32 20
#define STAGE_U (128 * ROWP32)
#define NSTG 3
__global__ __launch_bounds__(256, 2) void gemm_mma(
    const __nv_bfloat16* __restrict__ A, const __nv_bfloat16* __restrict__ Bt,
    const float* __restrict__ bias, float* __restrict__ C, int N)
{
    __shared__ __align__(16) uint32_t As[NSTG][STAGE_U];
    __shared__ __align__(16) uint32_t Bs[NSTG][STAGE_U];

    int tid = threadIdx.x;
    int wid = tid >> 5, lane = tid & 31;
    int wr = wid >> 2, wc = wid & 3;
    int lg = lane >> 2, lk = lane & 3;
    int bm = blockIdx.y * 128, bn = blockIdx.x * 128;

    int ldr = tid >> 1;
    int half = tid & 1;
    int ebase = half * 16;
    int c2base = half * 8;

    const __nv_bfloat16* Ag = A  + (size_t)(bm + ldr) * GK + ebase;
    const __nv_bfloat16* Bg = Bt + (size_t)(bn + ldr) * GK + ebase;

    uint32_t sAs = smem_u32(&As[0][0]);
    uint32_t sBs = smem_u32(&Bs[0][0]);
    uint32_t soff = (uint32_t)(ldr * ROWP32 + c2base) * 4;

    uint32_t a_off = (uint32_t)((wr * 64 + (lane & 15)) * 80 + ((lane >> 4) & 1) * 16);
    uint32_t b_off = (uint32_t)((wc * 32 + (lane & 7) + ((lane >> 4) & 1) * 8) * 80
                                + ((lane >> 3) & 1) * 16);

    float acc[4][4][4];
#pragma unroll
    for (int i = 0; i < 4; i++)
#pragma unroll
        for (int j = 0; j < 4; j++)
#pragma unroll
            for (int k = 0; k < 4; k++) acc[i][j][k] = 0.f;

#pragma unroll
    for (int s = 0; s < 2; s++) {
        int kc = s * 32;
        uint32_t ab = sAs + s * (STAGE_U * 4) + soff;
        uint32_t bb = sBs + s * (STAGE_U * 4) + soff;
        cp16(ab,      Ag + kc);
        cp16(ab + 16, Ag + kc + 8);
        cp16(bb,      Bg + kc);
        cp16(bb + 16, Bg + kc + 8);
        CP_COMMIT();
    }

    for (int it = 0; it < KCHUNKS; it++) {
        CP_WAIT1();
        __syncthreads();
        if (it + 2 < KCHUNKS) {
            int s = (it + 2) % NSTG;
            int kc = (it + 2) * 32;
            uint32_t ab = sAs + s * (STAGE_U * 4) + soff;
            uint32_t bb = sBs + s * (STAGE_U * 4) + soff;
            cp16(ab,      Ag + kc);
            cp16(ab + 16, Ag + kc + 8);
            cp16(bb,      Bg + kc);
            cp16(bb + 16, Bg + kc + 8);
        }
        CP_COMMIT();

        uint32_t aS = sAs + (it % NSTG) * (STAGE_U * 4) + a_off;
        uint32_t bS = sBs + (it % NSTG) * (STAGE_U * 4) + b_off;
#pragma unroll
        for (int ks = 0; ks < 2; ks++) {
            uint32_t af[4][4], bf[4][2];
#pragma unroll
            for (int mt = 0; mt < 4; mt++)
                ldsm_x4(af[mt], aS + mt * (16 * 80) + ks * 32);
#pragma unroll
            for (int j = 0; j < 2; j++)
                ldsm_x4(&bf[2 * j][0], bS + j * (16 * 80) + ks * 32);
#pragma unroll
            for (int mt = 0; mt < 4; mt++)
#pragma unroll
                for (int nt = 0; nt < 4; nt++)
                    mma_bf16(acc[mt][nt], af[mt], bf[nt]);
        }
    }

#pragma unroll
    for (int mt = 0; mt < 4; mt++) {
        size_t r0 = (size_t)(bm + wr * 64 + mt * 16 + lg);
#pragma unroll
        for (int nt = 0; nt < 4; nt++) {
            int c0 = bn + wc * 32 + nt * 8 + lk * 2;
            float bx = bias[c0], by = bias[c0 + 1];
            float2 v0 = make_float2(acc[mt][nt][0] + bx, acc[mt][nt][1] + by);
            float2 v1 = make_float2(acc[mt][nt][2] + bx, acc[mt][nt][3] + by);
            *(float2*)(C + r0 * N + c0) = v0;
            *(float2*)(C + (r0 + 8) * N + c0) = v1;
        }
    }
}

// ---------------- temporal attention, S=16 (float4 staging) ----------------
__global__ __launch_bounds__(256) void attn16_kernel(
    const float* __restrict__ qkv, __nv_bfloat16* __restrict__ out)
{
    __shared__ __align__(16) float Qs[16][68];
    __shared__ __align__(16) float Ks[16][68];
    __shared__ __align__(16) float Vs[16][64];
    __shared__ float Ps[16][17];

    int h = blockIdx.y;
    int seq = blockIdx.x;
    int b = seq / Pp, p = seq % Pp;
    int base = b * Ff * Pp + p;
    int tid = threadIdx.x;

    // stage Q, K, V: one float4 of each per thread (16 rows x 16 float4s)
    {
        int f = tid >> 4, d4 = (tid & 15) * 4;
        const float* row = qkv + (size_t)(base + f * Pp) * QKVW + h * HD + d4;
        float4 q4 = *(const float4*)(row);
        float4 k4 = *(const float4*)(row + Dd);
        float4 v4 = *(const float4*)(row + 2 * Dd);
        *(float4*)(&Qs[f][d4]) = q4;
        *(float4*)(&Ks[f][d4]) = k4;
        *(float4*)(&Vs[f][d4]) = v4;
    }
    __syncthreads();

    {
        int q = tid >> 4, k = tid & 15;
        float acc = 0.f;
#pragma unroll
        for (int d4 = 0; d4 < 16; d4++) {
            float4 kv = *(const float4*)(&Ks[k][d4 * 4]);
            float4 qv = *(const float4*)(&Qs[q][d4 * 4]);
            acc += qv.x * kv.x + qv.y * kv.y + qv.z * kv.z + qv.w * kv.w;
        }
        acc *= 0.125f;
        float m = acc;
#pragma unroll
        for (int o = 8; o; o >>= 1) m = fmaxf(m, __shfl_xor_sync(0xffffffffu, m, o));
        float e = __expf(acc - m);
        float s = e;
#pragma unroll
        for (int o = 8; o; o >>= 1) s += __shfl_xor_sync(0xffffffffu, s, o);
        Ps[q][k] = e / s;
    }
    __syncthreads();

    {
        int d = tid & 63;
        int q0 = (tid >> 6) * 4;
        float a0 = 0.f, a1 = 0.f, a2 = 0.f, a3 = 0.f;
#pragma unroll
        for (int k = 0; k < 16; k++) {
            float v = Vs[k][d];
            a0 += Ps[q0 + 0][k] * v;
            a1 += Ps[q0 + 1][k] * v;
            a2 += Ps[q0 + 2][k] * v;
            a3 += Ps[q0 + 3][k] * v;
        }
        size_t o0 = (size_t)(base + (q0 + 0) * Pp) * Dd + h * HD + d;
        out[o0]                       = __float2bfloat16(a0);
        out[o0 + (size_t)Pp * Dd]     = __float2bfloat16(a1);
        out[o0 + (size_t)2 * Pp * Dd] = __float2bfloat16(a2);
        out[o0 + (size_t)3 * Pp * Dd] = __float2bfloat16(a3);
    }
}

// ---------------- spatial attention, S=196 padded to 208, bf16 MMA ----------
#define SPAD 208
#define QRU 36
#define VTR 108
__global__ __launch_bounds__(256) void attn196_kernel(
    const float* __restrict__ qkv, __nv_bfloat16* __restrict__ out)
{
    extern __shared__ __align__(16) uint32_t sm196[];
    uint32_t* Qu = sm196;
    uint32_t* Ku = Qu + SPAD * QRU;
    uint32_t* Vu = Ku + SPAD * QRU;
    uint32_t* Tu = Vu + SPAD * QRU;

    int h = blockIdx.y;
    int base = blockIdx.x * Pp;
    int tid = threadIdx.x;
    int wid = tid >> 5, lane = tid & 31;
    int lg = lane >> 2, lk = lane & 3;

    for (int i = tid; i < SPAD * 16; i += 256) {
        int s = i >> 4, d4 = (i & 15) * 2;   // d4: u32 pair index (4 floats)
        uint32_t q0 = 0, q1 = 0, k0 = 0, k1 = 0, v0 = 0, v1 = 0;
        if (s < Pp) {
            const float* row = qkv + (size_t)(base + s) * QKVW + h * HD + d4 * 2;
            float4 q4 = *(const float4*)(row);
            float4 k4 = *(const float4*)(row + Dd);
            float4 v4 = *(const float4*)(row + 2 * Dd);
            q0 = packbf(q4.x, q4.y); q1 = packbf(q4.z, q4.w);
            k0 = packbf(k4.x, k4.y); k1 = packbf(k4.z, k4.w);
            v0 = packbf(v4.x, v4.y); v1 = packbf(v4.z, v4.w);
        }
        Qu[s * QRU + d4] = q0; Qu[s * QRU + d4 + 1] = q1;
        Ku[s * QRU + d4] = k0; Ku[s * QRU + d4 + 1] = k1;
        Vu[s * QRU + d4] = v0; Vu[s * QRU + d4 + 1] = v1;
    }
    __syncthreads();

    {
        const __nv_bfloat16* vb = (const __nv_bfloat16*)Vu;
        for (int i = tid; i < 64 * 104; i += 256) {
            int d = i & 63, s2 = i >> 6;
            uint32_t lo = *(const uint16_t*)(vb + (2 * s2) * (QRU * 2) + d);
            uint32_t hi = *(const uint16_t*)(vb + (2 * s2 + 1) * (QRU * 2) + d);
            Tu[d * VTR + s2] = lo | (hi << 16);
        }
    }
    __syncthreads();

    for (int mt = wid; mt < 13; mt += 8) {
        int r = mt * 16 + lg;

        uint32_t qa[4][4];
#pragma unroll
        for (int kc = 0; kc < 4; kc++) {
            int c2 = kc * 8 + lk;
            qa[kc][0] = Qu[r * QRU + c2];
            qa[kc][1] = Qu[(r + 8) * QRU + c2];
            qa[kc][2] = Qu[r * QRU + c2 + 4];
            qa[kc][3] = Qu[(r + 8) * QRU + c2 + 4];
        }

        float sc[26][4];
#pragma unroll
        for (int nt = 0; nt < 26; nt++)
            sc[nt][0] = sc[nt][1] = sc[nt][2] = sc[nt][3] = 0.f;
#pragma unroll
        for (int nt = 0; nt < 26; nt++) {
            int n = nt * 8 + lg;
#pragma unroll
            for (int kc = 0; kc < 4; kc++) {
                uint32_t b[2];
                b[0] = Ku[n * QRU + kc * 8 + lk];
                b[1] = Ku[n * QRU + kc * 8 + lk + 4];
                mma_bf16(sc[nt], qa[kc], b);
            }
        }

#pragma unroll
        for (int nt = 0; nt < 26; nt++) {
            int col0 = nt * 8 + 2 * lk;
            sc[nt][0] = (col0     < Pp) ? sc[nt][0] * 0.125f : -1e30f;
            sc[nt][1] = (col0 + 1 < Pp) ? sc[nt][1] * 0.125f : -1e30f;
            sc[nt][2] = (col0     < Pp) ? sc[nt][2] * 0.125f : -1e30f;
            sc[nt][3] = (col0 + 1 < Pp) ? sc[nt][3] * 0.125f : -1e30f;
        }

        float m0 = -1e30f, m1 = -1e30f;
#pragma unroll
        for (int nt = 0; nt < 26; nt++) {
            m0 = fmaxf(m0, fmaxf(sc[nt][0], sc[nt][1]));
            m1 = fmaxf(m1, fmaxf(sc[nt][2], sc[nt][3]));
        }
        m0 = fmaxf(m0, __shfl_xor_sync(0xffffffffu, m0, 1));
        m0 = fmaxf(m0, __shfl_xor_sync(0xffffffffu, m0, 2));
        m1 = fmaxf(m1, __shfl_xor_sync(0xffffffffu, m1, 1));
        m1 = fmaxf(m1, __shfl_xor_sync(0xffffffffu, m1, 2));

        float s0 = 0.f, s1 = 0.f;
#pragma unroll
        for (int nt = 0; nt < 26; nt++) {
            sc[nt][0] = __expf(sc[nt][0] - m0); s0 += sc[nt][0];
            sc[nt][1] = __expf(sc[nt][1] - m0); s0 += sc[nt][1];
            sc[nt][2] = __expf(sc[nt][2] - m1); s1 += sc[nt][2];
            sc[nt][3] = __expf(sc[nt][3] - m1); s1 += sc[nt][3];
        }
        s0 += __shfl_xor_sync(0xffffffffu, s0, 1);
        s0 += __shfl_xor_sync(0xffffffffu, s0, 2);
        s1 += __shfl_xor_sync(0xffffffffu, s1, 1);
        s1 += __shfl_xor_sync(0xffffffffu, s1, 2);

        uint32_t pk[13][4];
#pragma unroll
        for (int j = 0; j < 13; j++) {
            pk[j][0] = packbf(sc[2 * j][0],     sc[2 * j][1]);
            pk[j][1] = packbf(sc[2 * j][2],     sc[2 * j][3]);
            pk[j][2] = packbf(sc[2 * j + 1][0], sc[2 * j + 1][1]);
            pk[j][3] = packbf(sc[2 * j + 1][2], sc[2 * j + 1][3]);
        }

        float oa[8][4];
#pragma unroll
        for (int nd = 0; nd < 8; nd++)
            oa[nd][0] = oa[nd][1] = oa[nd][2] = oa[nd][3] = 0.f;
#pragma unroll
        for (int j = 0; j < 13; j++) {
#pragma unroll
            for (int nd = 0; nd < 8; nd++) {
                int n = nd * 8 + lg;
                uint32_t b[2];
                b[0] = Tu[n * VTR + j * 8 + lk];
                b[1] = Tu[n * VTR + j * 8 + lk + 4];
                mma_bf16(oa[nd], pk[j], b);
            }
        }

        float inv0 = 1.0f / s0, inv1 = 1.0f / s1;
        int row0 = r, row1 = r + 8;
#pragma unroll
        for (int nd = 0; nd < 8; nd++) {
            int col = nd * 8 + 2 * lk;
            if (row0 < Pp) {
                uint32_t u = packbf(oa[nd][0] * inv0, oa[nd][1] * inv0);
                *(uint32_t*)(out + (size_t)(base + row0) * Dd + h * HD + col) = u;
            }
            if (row1 < Pp) {
                uint32_t u = packbf(oa[nd][2] * inv1, oa[nd][3] * inv1);
                *(uint32_t*)(out + (size_t)(base + row1) * Dd + h * HD + col) = u;
            }
        }
    }
}

// ---------------- fused residual + LayerNorm (register-resident row) ---------
__global__ __launch_bounds__(256) void add_ln_kernel(
    const float* __restrict__ x, const float* __restrict__ y,
    const float* __restrict__ g, const float* __restrict__ b,
    float* __restrict__ out, __nv_bfloat16* __restrict__ outb, int wb)
{
    __shared__ float ps[8], ps2[8];
    __shared__ float red[2];

    size_t row = blockIdx.x;
    const float* xr = x + row * Dd;
    const float* yr = y + row * Dd;
    int tid = threadIdx.x;
    int lane = tid & 31, wid = tid >> 5;

    float v[3];
    float s = 0.f, s2 = 0.f;
#pragma unroll
    for (int k = 0; k < 3; k++) {
        int d = tid + k * 256;
        v[k] = xr[d] + yr[d];
        s += v[k];
        s2 += v[k] * v[k];
    }
#pragma unroll
    for (int o = 16; o; o >>= 1) {
        s  += __shfl_xor_sync(0xffffffffu, s, o);
        s2 += __shfl_xor_sync(0xffffffffu, s2, o);
    }
    if (lane == 0) { ps[wid] = s; ps2[wid] = s2; }
    __syncthreads();
    if (tid < 8) {
        s = ps[tid]; s2 = ps2[tid];
#pragma unroll
        for (int o = 4; o; o >>= 1) {
            s  += __shfl_xor_sync(0xffu, s, o);
            s2 += __shfl_xor_sync(0xffu, s2, o);
        }
        if (tid == 0) {
            float mean = s / Dd;
            float var = s2 / Dd - mean * mean;
            red[0] = mean;
            red[1] = rsqrtf(var + 1e-5f);
        }
    }
    __syncthreads();
    float mean = red[0], rstd = red[1];
#pragma unroll
    for (int k = 0; k < 3; k++) {
        int d = tid + k * 256;
        float o = (v[k] - mean) * rstd * g[d] + b[d];
        out[row * Dd + d] = o;
        if (wb) outb[row * Dd + d] = __float2bfloat16(o);
    }
}

// ---------------- launch ----------------
extern "C" void kernel_launch(void* const* d_in, const int* in_sizes, int n_in,
                              void* d_out, int out_size)
{
    const float* x      = (const float*)d_in[0];
    const float* Wqkv_t = (const float*)d_in[1];
    const float* bqkv_t = (const float*)d_in[2];
    const float* Wo_t   = (const float*)d_in[3];
    const float* bo_t   = (const float*)d_in[4];
    const float* Wqkv_s = (const float*)d_in[5];
    const float* bqkv_s = (const float*)d_in[6];
    const float* Wo_s   = (const float*)d_in[7];
    const float* bo_s   = (const float*)d_in[8];
    const float* g1     = (const float*)d_in[9];
    const float* b1     = (const float*)d_in[10];
    const float* g2     = (const float*)d_in[11];
    const float* b2     = (const float*)d_in[12];
    float* out = (float*)d_out;

    float *qkv, *y, *x1;
    __nv_bfloat16 *xb, *x1b, *attnb, *wtb;
    cudaGetSymbolAddress((void**)&qkv,   g_qkv);
    cudaGetSymbolAddress((void**)&y,     g_y);
    cudaGetSymbolAddress((void**)&x1,    g_x1);
    cudaGetSymbolAddress((void**)&xb,    g_xb);
    cudaGetSymbolAddress((void**)&x1b,   g_x1b);
    cudaGetSymbolAddress((void**)&attnb, g_attnb);
    cudaGetSymbolAddress((void**)&wtb,   g_wtb);

    const int SMEM196 = (3 * SPAD * QRU + 64 * VTR) * (int)sizeof(uint32_t);  // 117504
    cudaFuncSetAttribute(attn196_kernel, cudaFuncAttributeMaxDynamicSharedMemorySize, SMEM196);

    dim3 tb(32, 8);
    dim3 tg_qkv(QKVW / 32, GK / 32);      // (72, 24)
    dim3 tg_out(Dd / 32, GK / 32);        // (24, 24)
    dim3 gg_qkv(QKVW / 128, NTOK / 128);  // (18, 196)
    dim3 gg_out(Dd / 128, NTOK / 128);    // (6, 196)
    int n4 = NTOK * Dd / 4;

    // x -> bf16
    f2b_kernel<<<(n4 + 255) / 256, 256>>>(x, xb, n4);
    // temporal QKV projection
    transpose_b<<<tg_qkv, tb>>>(Wqkv_t, wtb, GK, QKVW);
    gemm_mma<<<gg_qkv, 256>>>(xb, wtb, bqkv_t, qkv, QKVW);
    // temporal attention (S=16)
    attn16_kernel<<<dim3(Bb * Pp, Hh), 256>>>(qkv, attnb);
    // temporal out-projection
    transpose_b<<<tg_out, tb>>>(Wo_t, wtb, GK, Dd);
    gemm_mma<<<gg_out, 256>>>(attnb, wtb, bo_t, y, Dd);
    // x1 = LN(x + y)  (+ bf16 copy)
    add_ln_kernel<<<NTOK, 256>>>(x, y, g1, b1, x1, x1b, 1);
    // spatial QKV projection
    transpose_b<<<tg_qkv, tb>>>(Wqkv_s, wtb, GK, QKVW);
    gemm_mma<<<gg_qkv, 256>>>(x1b, wtb, bqkv_s, qkv, QKVW);
    // spatial attention (S=196), bf16 MMA flash-style
    attn196_kernel<<<dim3(Bb * Ff, Hh), 256, SMEM196>>>(qkv, attnb);
    // spatial out-projection
    transpose_b<<<tg_out, tb>>>(Wo_s, wtb, GK, Dd);
    gemm_mma<<<gg_out, 256>>>(attnb, wtb, bo_s, y, Dd);
    // out = LN(x1 + y)
    add_ln_kernel<<<NTOK, 256>>>(x1, y, g2, b2, out, (__nv_bfloat16*)nullptr, 0);
}

// round 14
// speedup vs baseline: 1.2961x; 1.0142x over previous
#include <cuda_runtime.h>
#include <cuda_bf16.h>
#include <cstdint>

#define Bb 8
#define Ff 16
#define Pp 196
#define Dd 768
#define Hh 12
#define HD 64
#define NTOK (Bb*Ff*Pp)          // 25088
#define QKVW (3*Dd)              // 2304
#define GK 768                   // K for all GEMMs
#define KCHUNKS (GK/32)          // 24

// ---------------- scratch (allocation-free: __device__ globals) ----------------
__device__ __nv_bfloat16 g_qkvb[(size_t)NTOK * QKVW];  // 115 MB (bf16 qkv)
__device__ float         g_y[(size_t)NTOK * Dd];       // 77 MB
__device__ float         g_x1[(size_t)NTOK * Dd];      // 77 MB
__device__ __nv_bfloat16 g_xb[(size_t)NTOK * Dd];      // 38.5 MB
__device__ __nv_bfloat16 g_x1b[(size_t)NTOK * Dd];     // 38.5 MB
__device__ __nv_bfloat16 g_attnb[(size_t)NTOK * Dd];   // 38.5 MB
__device__ __nv_bfloat16 g_wtb[(size_t)Dd * QKVW];     // 3.5 MB

__device__ __forceinline__ void mma_bf16(float* c, const uint32_t* a, const uint32_t* b) {
    asm volatile(
        "mma.sync.aligned.m16n8k16.row.col.f32.bf16.bf16.f32 "
        "{%0,%1,%2,%3}, {%4,%5,%6,%7}, {%8,%9}, {%0,%1,%2,%3};"
        : "+f"(c[0]), "+f"(c[1]), "+f"(c[2]), "+f"(c[3])
        : "r"(a[0]), "r"(a[1]), "r"(a[2]), "r"(a[3]), "r"(b[0]), "r"(b[1]));
}
__device__ __forceinline__ void ldsm_x4(uint32_t* r, uint32_t addr) {
    asm volatile("ldmatrix.sync.aligned.m8n8.x4.shared.b16 {%0,%1,%2,%3}, [%4];"
        : "=r"(r[0]), "=r"(r[1]), "=r"(r[2]), "=r"(r[3]) : "r"(addr));
}
__device__ __forceinline__ uint32_t smem_u32(const void* p) {
    uint32_t a;
    asm("{ .reg .u64 t; cvta.to.shared.u64 t, %1; cvt.u32.u64 %0, t; }" : "=r"(a) : "l"(p));
    return a;
}
__device__ __forceinline__ void cp16(uint32_t dst, const void* src) {
    asm volatile("cp.async.cg.shared.global [%0], [%1], 16;" :: "r"(dst), "l"(src));
}
#define CP_COMMIT() asm volatile("cp.async.commit_group;" ::: "memory")
#define CP_WAIT1()  asm volatile("cp.async.wait_group 1;" ::: "memory")

__device__ __forceinline__ uint32_t packbf(float lo, float hi) {
    __nv_bfloat162 p = __float22bfloat162_rn(make_float2(lo, hi));
    return *reinterpret_cast<uint32_t*>(&p);
}
__device__ __forceinline__ float2 ubf2(uint32_t u) {
    __nv_bfloat162 p = *reinterpret_cast<__nv_bfloat162*>(&u);
    return __bfloat1622float2(p);
}

// ---------------- f32 -> bf16 convert ----------------
__global__ __launch_bounds__(256) void f2b_kernel(
    const float* __restrict__ in, __nv_bfloat16* __restrict__ out, int n4)
{
    int i = blockIdx.x * 256 + threadIdx.x;
    if (i < n4) {
        float4 v = *(const float4*)(in + (size_t)i * 4);
        uint2 u;
        u.x = packbf(v.x, v.y);
        u.y = packbf(v.z, v.w);
        *(uint2*)(out + (size_t)i * 4) = u;
    }
}

// ---------------- weight transpose to bf16: out[N,K] = bf16(in[K,N]) ----------
__global__ __launch_bounds__(256) void transpose_b(
    const float* __restrict__ in, __nv_bfloat16* __restrict__ out, int K, int N)
{
    __shared__ float t[32][33];
    int n0 = blockIdx.x * 32, k0 = blockIdx.y * 32;
    int tx = threadIdx.x, ty = threadIdx.y;   // 32 x 8
#pragma unroll
    for (int j = 0; j < 32; j += 8)
        t[ty + j][tx] = in[(size_t)(k0 + ty + j) * N + n0 + tx];
    __syncthreads();
#pragma unroll
    for (int j = 0; j < 32; j += 8)
        out[(size_t)(n0 + ty + j) * K + k0 + tx] = __float2bfloat16(t[tx][ty + j]);
}

// ---------------- BF16 mma.sync GEMM, cp.async + ldmatrix -------------------
// 128x128 CTA tile, BK=32, 256 threads (8 warps 2x4, warp tile 64x32), 2 CTA/SM.
// obf=1: store bf16 to C16; obf=0: store f32 to C.
#define ROWP32 20
#define STAGE_U (128 * ROWP32)
#define NSTG 3
__global__ __launch_bounds__(256, 2) void gemm_mma(
    const __nv_bfloat16* __restrict__ A, const __nv_bfloat16* __restrict__ Bt,
    const float* __restrict__ bias, float* __restrict__ C,
    __nv_bfloat16* __restrict__ C16, int N, int obf)
{
    __shared__ __align__(16) uint32_t As[NSTG][STAGE_U];
    __shared__ __align__(16) uint32_t Bs[NSTG][STAGE_U];

    int tid = threadIdx.x;
    int wid = tid >> 5, lane = tid & 31;
    int wr = wid >> 2, wc = wid & 3;
    int lg = lane >> 2, lk = lane & 3;
    int bm = blockIdx.y * 128, bn = blockIdx.x * 128;

    int ldr = tid >> 1;
    int half = tid & 1;
    int ebase = half * 16;
    int c2base = half * 8;

    const __nv_bfloat16* Ag = A  + (size_t)(bm + ldr) * GK + ebase;
    const __nv_bfloat16* Bg = Bt + (size_t)(bn + ldr) * GK + ebase;

    uint32_t sAs = smem_u32(&As[0][0]);
    uint32_t sBs = smem_u32(&Bs[0][0]);
    uint32_t soff = (uint32_t)(ldr * ROWP32 + c2base) * 4;

    uint32_t a_off = (uint32_t)((wr * 64 + (lane & 15)) * 80 + ((lane >> 4) & 1) * 16);
    uint32_t b_off = (uint32_t)((wc * 32 + (lane & 7) + ((lane >> 4) & 1) * 8) * 80
                                + ((lane >> 3) & 1) * 16);

    float acc[4][4][4];
#pragma unroll
    for (int i = 0; i < 4; i++)
#pragma unroll
        for (int j = 0; j < 4; j++)
#pragma unroll
            for (int k = 0; k < 4; k++) acc[i][j][k] = 0.f;

#pragma unroll
    for (int s = 0; s < 2; s++) {
        int kc = s * 32;
        uint32_t ab = sAs + s * (STAGE_U * 4) + soff;
        uint32_t bb = sBs + s * (STAGE_U * 4) + soff;
        cp16(ab,      Ag + kc);
        cp16(ab + 16, Ag + kc + 8);
        cp16(bb,      Bg + kc);
        cp16(bb + 16, Bg + kc + 8);
        CP_COMMIT();
    }

    for (int it = 0; it < KCHUNKS; it++) {
        CP_WAIT1();
        __syncthreads();
        if (it + 2 < KCHUNKS) {
            int s = (it + 2) % NSTG;
            int kc = (it + 2) * 32;
            uint32_t ab = sAs + s * (STAGE_U * 4) + soff;
            uint32_t bb = sBs + s * (STAGE_U * 4) + soff;
            cp16(ab,      Ag + kc);
            cp16(ab + 16, Ag + kc + 8);
            cp16(bb,      Bg + kc);
            cp16(bb + 16, Bg + kc + 8);
        }
        CP_COMMIT();

        uint32_t aS = sAs + (it % NSTG) * (STAGE_U * 4) + a_off;
        uint32_t bS = sBs + (it % NSTG) * (STAGE_U * 4) + b_off;
#pragma unroll
        for (int ks = 0; ks < 2; ks++) {
            uint32_t af[4][4], bf[4][2];
#pragma unroll
            for (int mt = 0; mt < 4; mt++)
                ldsm_x4(af[mt], aS + mt * (16 * 80) + ks * 32);
#pragma unroll
            for (int j = 0; j < 2; j++)
                ldsm_x4(&bf[2 * j][0], bS + j * (16 * 80) + ks * 32);
#pragma unroll
            for (int mt = 0; mt < 4; mt++)
#pragma unroll
                for (int nt = 0; nt < 4; nt++)
                    mma_bf16(acc[mt][nt], af[mt], bf[nt]);
        }
    }

#pragma unroll
    for (int mt = 0; mt < 4; mt++) {
        size_t r0 = (size_t)(bm + wr * 64 + mt * 16 + lg);
#pragma unroll
        for (int nt = 0; nt < 4; nt++) {
            int c0 = bn + wc * 32 + nt * 8 + lk * 2;
            float bx = bias[c0], by = bias[c0 + 1];
            float v00 = acc[mt][nt][0] + bx, v01 = acc[mt][nt][1] + by;
            float v10 = acc[mt][nt][2] + bx, v11 = acc[mt][nt][3] + by;
            if (obf) {
                *(uint32_t*)(C16 + r0 * N + c0)       = packbf(v00, v01);
                *(uint32_t*)(C16 + (r0 + 8) * N + c0) = packbf(v10, v11);
            } else {
                *(float2*)(C + r0 * N + c0)       = make_float2(v00, v01);
                *(float2*)(C + (r0 + 8) * N + c0) = make_float2(v10, v11);
            }
        }
    }
}

// ---------------- temporal attention, S=16 (bf16 qkv input) ----------------
__global__ __launch_bounds__(256) void attn16_kernel(
    const __nv_bfloat16* __restrict__ qkv, __nv_bfloat16* __restrict__ out)
{
    __shared__ __align__(16) float Qs[16][68];
    __shared__ __align__(16) float Ks[16][68];
    __shared__ __align__(16) float Vs[16][64];
    __shared__ float Ps[16][17];

    int h = blockIdx.y;
    int seq = blockIdx.x;
    int b = seq / Pp, p = seq % Pp;
    int base = b * Ff * Pp + p;
    int tid = threadIdx.x;

    // stage Q, K, V: 4 bf16 of each per thread (uint2 loads), unpack to f32
    {
        int f = tid >> 4, d4 = (tid & 15) * 4;
        const __nv_bfloat16* row = qkv + (size_t)(base + f * Pp) * QKVW + h * HD + d4;
        uint2 qu = *(const uint2*)(row);
        uint2 ku = *(const uint2*)(row + Dd);
        uint2 vu = *(const uint2*)(row + 2 * Dd);
        float2 qa = ubf2(qu.x), qb = ubf2(qu.y);
        float2 ka = ubf2(ku.x), kb = ubf2(ku.y);
        float2 va = ubf2(vu.x), vb = ubf2(vu.y);
        *(float4*)(&Qs[f][d4]) = make_float4(qa.x, qa.y, qb.x, qb.y);
        *(float4*)(&Ks[f][d4]) = make_float4(ka.x, ka.y, kb.x, kb.y);
        *(float4*)(&Vs[f][d4]) = make_float4(va.x, va.y, vb.x, vb.y);
    }
    __syncthreads();

    {
        int q = tid >> 4, k = tid & 15;
        float acc = 0.f;
#pragma unroll
        for (int d4 = 0; d4 < 16; d4++) {
            float4 kv = *(const float4*)(&Ks[k][d4 * 4]);
            float4 qv = *(const float4*)(&Qs[q][d4 * 4]);
            acc += qv.x * kv.x + qv.y * kv.y + qv.z * kv.z + qv.w * kv.w;
        }
        acc *= 0.125f;
        float m = acc;
#pragma unroll
        for (int o = 8; o; o >>= 1) m = fmaxf(m, __shfl_xor_sync(0xffffffffu, m, o));
        float e = __expf(acc - m);
        float s = e;
#pragma unroll
        for (int o = 8; o; o >>= 1) s += __shfl_xor_sync(0xffffffffu, s, o);
        Ps[q][k] = e / s;
    }
    __syncthreads();

    {
        int d = tid & 63;
        int q0 = (tid >> 6) * 4;
        float a0 = 0.f, a1 = 0.f, a2 = 0.f, a3 = 0.f;
#pragma unroll
        for (int k = 0; k < 16; k++) {
            float v = Vs[k][d];
            a0 += Ps[q0 + 0][k] * v;
            a1 += Ps[q0 + 1][k] * v;
            a2 += Ps[q0 + 2][k] * v;
            a3 += Ps[q0 + 3][k] * v;
        }
        size_t o0 = (size_t)(base + (q0 + 0) * Pp) * Dd + h * HD + d;
        out[o0]                       = __float2bfloat16(a0);
        out[o0 + (size_t)Pp * Dd]     = __float2bfloat16(a1);
        out[o0 + (size_t)2 * Pp * Dd] = __float2bfloat16(a2);
        out[o0 + (size_t)3 * Pp * Dd] = __float2bfloat16(a3);
    }
}

// ---------------- spatial attention, S=196 padded to 208, bf16 MMA ----------
#define SPAD 208
#define QRU 36
#define VTR 108
__global__ __launch_bounds__(256) void attn196_kernel(
    const __nv_bfloat16* __restrict__ qkv, __nv_bfloat16* __restrict__ out)
{
    extern __shared__ __align__(16) uint32_t sm196[];
    uint32_t* Qu = sm196;
    uint32_t* Ku = Qu + SPAD * QRU;
    uint32_t* Vu = Ku + SPAD * QRU;
    uint32_t* Tu = Vu + SPAD * QRU;

    int h = blockIdx.y;
    int base = blockIdx.x * Pp;
    int tid = threadIdx.x;
    int wid = tid >> 5, lane = tid & 31;
    int lg = lane >> 2, lk = lane & 3;

    // stage Q, K, V: direct bf16 u32 copies (rows >= 196 zeroed)
    for (int i = tid; i < SPAD * 16; i += 256) {
        int s = i >> 4, d4 = (i & 15) * 2;   // u32 pair index
        uint32_t q0 = 0, q1 = 0, k0 = 0, k1 = 0, v0 = 0, v1 = 0;
        if (s < Pp) {
            const __nv_bfloat16* row = qkv + (size_t)(base + s) * QKVW + h * HD + d4 * 2;
            uint2 qq = *(const uint2*)(row);
            uint2 kk = *(const uint2*)(row + Dd);
            uint2 vv = *(const uint2*)(row + 2 * Dd);
            q0 = qq.x; q1 = qq.y;
            k0 = kk.x; k1 = kk.y;
            v0 = vv.x; v1 = vv.y;
        }
        Qu[s * QRU + d4] = q0; Qu[s * QRU + d4 + 1] = q1;
        Ku[s * QRU + d4] = k0; Ku[s * QRU + d4 + 1] = k1;
        Vu[s * QRU + d4] = v0; Vu[s * QRU + d4 + 1] = v1;
    }
    __syncthreads();

    {
        const __nv_bfloat16* vb = (const __nv_bfloat16*)Vu;
        for (int i = tid; i < 64 * 104; i += 256) {
            int d = i & 63, s2 = i >> 6;
            uint32_t lo = *(const uint16_t*)(vb + (2 * s2) * (QRU * 2) + d);
            uint32_t hi = *(const uint16_t*)(vb + (2 * s2 + 1) * (QRU * 2) + d);
            Tu[d * VTR + s2] = lo | (hi << 16);
        }
    }
    __syncthreads();

    for (int mt = wid; mt < 13; mt += 8) {
        int r = mt * 16 + lg;

        uint32_t qa[4][4];
#pragma unroll
        for (int kc = 0; kc < 4; kc++) {
            int c2 = kc * 8 + lk;
            qa[kc][0] = Qu[r * QRU + c2];
            qa[kc][1] = Qu[(r + 8) * QRU + c2];
            qa[kc][2] = Qu[r * QRU + c2 + 4];
            qa[kc][3] = Qu[(r + 8) * QRU + c2 + 4];
        }

        float sc[26][4];
#pragma unroll
        for (int nt = 0; nt < 26; nt++)
            sc[nt][0] = sc[nt][1] = sc[nt][2] = sc[nt][3] = 0.f;
#pragma unroll
        for (int nt = 0; nt < 26; nt++) {
            int n = nt * 8 + lg;
#pragma unroll
            for (int kc = 0; kc < 4; kc++) {
                uint32_t b[2];
                b[0] = Ku[n * QRU + kc * 8 + lk];
                b[1] = Ku[n * QRU + kc * 8 + lk + 4];
                mma_bf16(sc[nt], qa[kc], b);
            }
        }

#pragma unroll
        for (int nt = 0; nt < 26; nt++) {
            int col0 = nt * 8 + 2 * lk;
            sc[nt][0] = (col0     < Pp) ? sc[nt][0] * 0.125f : -1e30f;
            sc[nt][1] = (col0 + 1 < Pp) ? sc[nt][1] * 0.125f : -1e30f;
            sc[nt][2] = (col0     < Pp) ? sc[nt][2] * 0.125f : -1e30f;
            sc[nt][3] = (col0 + 1 < Pp) ? sc[nt][3] * 0.125f : -1e30f;
        }

        float m0 = -1e30f, m1 = -1e30f;
#pragma unroll
        for (int nt = 0; nt < 26; nt++) {
            m0 = fmaxf(m0, fmaxf(sc[nt][0], sc[nt][1]));
            m1 = fmaxf(m1, fmaxf(sc[nt][2], sc[nt][3]));
        }
        m0 = fmaxf(m0, __shfl_xor_sync(0xffffffffu, m0, 1));
        m0 = fmaxf(m0, __shfl_xor_sync(0xffffffffu, m0, 2));
        m1 = fmaxf(m1, __shfl_xor_sync(0xffffffffu, m1, 1));
        m1 = fmaxf(m1, __shfl_xor_sync(0xffffffffu, m1, 2));

        float s0 = 0.f, s1 = 0.f;
#pragma unroll
        for (int nt = 0; nt < 26; nt++) {
            sc[nt][0] = __expf(sc[nt][0] - m0); s0 += sc[nt][0];
            sc[nt][1] = __expf(sc[nt][1] - m0); s0 += sc[nt][1];
            sc[nt][2] = __expf(sc[nt][2] - m1); s1 += sc[nt][2];
            sc[nt][3] = __expf(sc[nt][3] - m1); s1 += sc[nt][3];
        }
        s0 += __shfl_xor_sync(0xffffffffu, s0, 1);
        s0 += __shfl_xor_sync(0xffffffffu, s0, 2);
        s1 += __shfl_xor_sync(0xffffffffu, s1, 1);
        s1 += __shfl_xor_sync(0xffffffffu, s1, 2);

        uint32_t pk[13][4];
#pragma unroll
        for (int j = 0; j < 13; j++) {
            pk[j][0] = packbf(sc[2 * j][0],     sc[2 * j][1]);
            pk[j][1] = packbf(sc[2 * j][2],     sc[2 * j][3]);
            pk[j][2] = packbf(sc[2 * j + 1][0], sc[2 * j + 1][1]);
            pk[j][3] = packbf(sc[2 * j + 1][2], sc[2 * j + 1][3]);
        }

        float oa[8][4];
#pragma unroll
        for (int nd = 0; nd < 8; nd++)
            oa[nd][0] = oa[nd][1] = oa[nd][2] = oa[nd][3] = 0.f;
#pragma unroll
        for (int j = 0; j < 13; j++) {
#pragma unroll
            for (int nd = 0; nd < 8; nd++) {
                int n = nd * 8 + lg;
                uint32_t b[2];
                b[0] = Tu[n * VTR + j * 8 + lk];
                b[1] = Tu[n * VTR + j * 8 + lk + 4];
                mma_bf16(oa[nd], pk[j], b);
            }
        }

        float inv0 = 1.0f / s0, inv1 = 1.0f / s1;
        int row0 = r, row1 = r + 8;
#pragma unroll
        for (int nd = 0; nd < 8; nd++) {
            int col = nd * 8 + 2 * lk;
            if (row0 < Pp) {
                uint32_t u = packbf(oa[nd][0] * inv0, oa[nd][1] * inv0);
                *(uint32_t*)(out + (size_t)(base + row0) * Dd + h * HD + col) = u;
            }
            if (row1 < Pp) {
                uint32_t u = packbf(oa[nd][2] * inv1, oa[nd][3] * inv1);
                *(uint32_t*)(out + (size_t)(base + row1) * Dd + h * HD + col) = u;
            }
        }
    }
}

// ---------------- fused residual + LayerNorm (register-resident row) ---------
__global__ __launch_bounds__(256) void add_ln_kernel(
    const float* __restrict__ x, const float* __restrict__ y,
    const float* __restrict__ g, const float* __restrict__ b,
    float* __restrict__ out, __nv_bfloat16* __restrict__ outb, int wb)
{
    __shared__ float ps[8], ps2[8];
    __shared__ float red[2];

    size_t row = blockIdx.x;
    const float* xr = x + row * Dd;
    const float* yr = y + row * Dd;
    int tid = threadIdx.x;
    int lane = tid & 31, wid = tid >> 5;

    float v[3];
    float s = 0.f, s2 = 0.f;
#pragma unroll
    for (int k = 0; k < 3; k++) {
        int d = tid + k * 256;
        v[k] = xr[d] + yr[d];
        s += v[k];
        s2 += v[k] * v[k];
    }
#pragma unroll
    for (int o = 16; o; o >>= 1) {
        s  += __shfl_xor_sync(0xffffffffu, s, o);
        s2 += __shfl_xor_sync(0xffffffffu, s2, o);
    }
    if (lane == 0) { ps[wid] = s; ps2[wid] = s2; }
    __syncthreads();
    if (tid < 8) {
        s = ps[tid]; s2 = ps2[tid];
#pragma unroll
        for (int o = 4; o; o >>= 1) {
            s  += __shfl_xor_sync(0xffu, s, o);
            s2 += __shfl_xor_sync(0xffu, s2, o);
        }
        if (tid == 0) {
            float mean = s / Dd;
            float var = s2 / Dd - mean * mean;
            red[0] = mean;
            red[1] = rsqrtf(var + 1e-5f);
        }
    }
    __syncthreads();
    float mean = red[0], rstd = red[1];
#pragma unroll
    for (int k = 0; k < 3; k++) {
        int d = tid + k * 256;
        float o = (v[k] - mean) * rstd * g[d] + b[d];
        out[row * Dd + d] = o;
        if (wb) outb[row * Dd + d] = __float2bfloat16(o);
    }
}

// ---------------- launch ----------------
extern "C" void kernel_launch(void* const* d_in, const int* in_sizes, int n_in,
                              void* d_out, int out_size)
{
    const float* x      = (const float*)d_in[0];
    const float* Wqkv_t = (const float*)d_in[1];
    const float* bqkv_t = (const float*)d_in[2];
    const float* Wo_t   = (const float*)d_in[3];
    const float* bo_t   = (const float*)d_in[4];
    const float* Wqkv_s = (const float*)d_in[5];
    const float* bqkv_s = (const float*)d_in[6];
    const float* Wo_s   = (const float*)d_in[7];
    const float* bo_s   = (const float*)d_in[8];
    const float* g1     = (const float*)d_in[9];
    const float* b1     = (const float*)d_in[10];
    const float* g2     = (const float*)d_in[11];
    const float* b2     = (const float*)d_in[12];
    float* out = (float*)d_out;

    float *y, *x1;
    __nv_bfloat16 *qkvb, *xb, *x1b, *attnb, *wtb;
    cudaGetSymbolAddress((void**)&qkvb,  g_qkvb);
    cudaGetSymbolAddress((void**)&y,     g_y);
    cudaGetSymbolAddress((void**)&x1,    g_x1);
    cudaGetSymbolAddress((void**)&xb,    g_xb);
    cudaGetSymbolAddress((void**)&x1b,   g_x1b);
    cudaGetSymbolAddress((void**)&attnb, g_attnb);
    cudaGetSymbolAddress((void**)&wtb,   g_wtb);

    const int SMEM196 = (3 * SPAD * QRU + 64 * VTR) * (int)sizeof(uint32_t);  // 117504
    cudaFuncSetAttribute(attn196_kernel, cudaFuncAttributeMaxDynamicSharedMemorySize, SMEM196);

    dim3 tb(32, 8);
    dim3 tg_qkv(QKVW / 32, GK / 32);      // (72, 24)
    dim3 tg_out(Dd / 32, GK / 32);        // (24, 24)
    dim3 gg_qkv(QKVW / 128, NTOK / 128);  // (18, 196)
    dim3 gg_out(Dd / 128, NTOK / 128);    // (6, 196)
    int n4 = NTOK * Dd / 4;

    // x -> bf16
    f2b_kernel<<<(n4 + 255) / 256, 256>>>(x, xb, n4);
    // temporal QKV projection -> bf16 qkv
    transpose_b<<<tg_qkv, tb>>>(Wqkv_t, wtb, GK, QKVW);
    gemm_mma<<<gg_qkv, 256>>>(xb, wtb, bqkv_t, nullptr, qkvb, QKVW, 1);
    // temporal attention (S=16)
    attn16_kernel<<<dim3(Bb * Pp, Hh), 256>>>(qkvb, attnb);
    // temporal out-projection -> f32 y
    transpose_b<<<tg_out, tb>>>(Wo_t, wtb, GK, Dd);
    gemm_mma<<<gg_out, 256>>>(attnb, wtb, bo_t, y, nullptr, Dd, 0);
    // x1 = LN(x + y)  (+ bf16 copy)
    add_ln_kernel<<<NTOK, 256>>>(x, y, g1, b1, x1, x1b, 1);
    // spatial QKV projection -> bf16 qkv
    transpose_b<<<tg_qkv, tb>>>(Wqkv_s, wtb, GK, QKVW);
    gemm_mma<<<gg_qkv, 256>>>(x1b, wtb, bqkv_s, nullptr, qkvb, QKVW, 1);
    // spatial attention (S=196)
    attn196_kernel<<<dim3(Bb * Ff, Hh), 256, SMEM196>>>(qkvb, attnb);
    // spatial out-projection -> f32 y
    transpose_b<<<tg_out, tb>>>(Wo_s, wtb, GK, Dd);
    gemm_mma<<<gg_out, 256>>>(attnb, wtb, bo_s, y, nullptr, Dd, 0);
    // out = LN(x1 + y)
    add_ln_kernel<<<NTOK, 256>>>(x1, y, g2, b2, out, (__nv_bfloat16*)nullptr, 0);
}

// round 15
// speedup vs baseline: 1.3491x; 1.0409x over previous
#include <cuda_runtime.h>
#include <cuda_bf16.h>
#include <cstdint>

#define Bb 8
#define Ff 16
#define Pp 196
#define Dd 768
#define Hh 12
#define HD 64
#define NTOK (Bb*Ff*Pp)          // 25088
#define QKVW (3*Dd)              // 2304
#define GK 768                   // K for all GEMMs
#define KCHUNKS (GK/32)          // 24

// ---------------- scratch (allocation-free: __device__ globals) ----------------
__device__ __nv_bfloat16 g_qkvb[(size_t)NTOK * QKVW];  // 115 MB (bf16 qkv)
__device__ float         g_y[(size_t)NTOK * Dd];       // 77 MB
__device__ float         g_x1[(size_t)NTOK * Dd];      // 77 MB
__device__ __nv_bfloat16 g_xb[(size_t)NTOK * Dd];      // 38.5 MB
__device__ __nv_bfloat16 g_x1b[(size_t)NTOK * Dd];     // 38.5 MB
__device__ __nv_bfloat16 g_attnb[(size_t)NTOK * Dd];   // 38.5 MB
__device__ __nv_bfloat16 g_wtb[(size_t)Dd * QKVW];     // 3.5 MB

__device__ __forceinline__ void mma_bf16(float* c, const uint32_t* a, const uint32_t* b) {
    asm volatile(
        "mma.sync.aligned.m16n8k16.row.col.f32.bf16.bf16.f32 "
        "{%0,%1,%2,%3}, {%4,%5,%6,%7}, {%8,%9}, {%0,%1,%2,%3};"
        : "+f"(c[0]), "+f"(c[1]), "+f"(c[2]), "+f"(c[3])
        : "r"(a[0]), "r"(a[1]), "r"(a[2]), "r"(a[3]), "r"(b[0]), "r"(b[1]));
}
__device__ __forceinline__ void ldsm_x4(uint32_t* r, uint32_t addr) {
    asm volatile("ldmatrix.sync.aligned.m8n8.x4.shared.b16 {%0,%1,%2,%3}, [%4];"
        : "=r"(r[0]), "=r"(r[1]), "=r"(r[2]), "=r"(r[3]) : "r"(addr));
}
__device__ __forceinline__ uint32_t smem_u32(const void* p) {
    uint32_t a;
    asm("{ .reg .u64 t; cvta.to.shared.u64 t, %1; cvt.u32.u64 %0, t; }" : "=r"(a) : "l"(p));
    return a;
}
__device__ __forceinline__ void cp16(uint32_t dst, const void* src) {
    asm volatile("cp.async.cg.shared.global [%0], [%1], 16;" :: "r"(dst), "l"(src));
}
#define CP_COMMIT() asm volatile("cp.async.commit_group;" ::: "memory")
#define CP_WAIT1()  asm volatile("cp.async.wait_group 1;" ::: "memory")

__device__ __forceinline__ uint32_t packbf(float lo, float hi) {
    __nv_bfloat162 p = __float22bfloat162_rn(make_float2(lo, hi));
    return *reinterpret_cast<uint32_t*>(&p);
}
__device__ __forceinline__ float2 ubf2(uint32_t u) {
    __nv_bfloat162 p = *reinterpret_cast<__nv_bfloat162*>(&u);
    return __bfloat1622float2(p);
}

// ---------------- f32 -> bf16 convert ----------------
__global__ __launch_bounds__(256) void f2b_kernel(
    const float* __restrict__ in, __nv_bfloat16* __restrict__ out, int n4)
{
    int i = blockIdx.x * 256 + threadIdx.x;
    if (i < n4) {
        float4 v = *(const float4*)(in + (size_t)i * 4);
        uint2 u;
        u.x = packbf(v.x, v.y);
        u.y = packbf(v.z, v.w);
        *(uint2*)(out + (size_t)i * 4) = u;
    }
}

// ---------------- weight transpose to bf16: out[N,K] = bf16(in[K,N]) ----------
__global__ __launch_bounds__(256) void transpose_b(
    const float* __restrict__ in, __nv_bfloat16* __restrict__ out, int K, int N)
{
    __shared__ float t[32][33];
    int n0 = blockIdx.x * 32, k0 = blockIdx.y * 32;
    int tx = threadIdx.x, ty = threadIdx.y;   // 32 x 8
#pragma unroll
    for (int j = 0; j < 32; j += 8)
        t[ty + j][tx] = in[(size_t)(k0 + ty + j) * N + n0 + tx];
    __syncthreads();
#pragma unroll
    for (int j = 0; j < 32; j += 8)
        out[(size_t)(n0 + ty + j) * K + k0 + tx] = __float2bfloat16(t[tx][ty + j]);
}

// ---------------- BF16 mma.sync GEMM, cp.async + ldmatrix -------------------
// 128x128 CTA tile, BK=32, 256 threads (8 warps 2x4, warp tile 64x32), 2 CTA/SM.
// obf=1: store bf16 to C16; obf=0: store f32 to C.
#define ROWP32 20
#define STAGE_U (128 * ROWP32)
#define NSTG 3
__global__ __launch_bounds__(256, 2) void gemm_mma(
    const __nv_bfloat16* __restrict__ A, const __nv_bfloat16* __restrict__ Bt,
    const float* __restrict__ bias, float* __restrict__ C,
    __nv_bfloat16* __restrict__ C16, int N, int obf)
{
    __shared__ __align__(16) uint32_t As[NSTG][STAGE_U];
    __shared__ __align__(16) uint32_t Bs[NSTG][STAGE_U];

    int tid = threadIdx.x;
    int wid = tid >> 5, lane = tid & 31;
    int wr = wid >> 2, wc = wid & 3;
    int lg = lane >> 2, lk = lane & 3;
    int bm = blockIdx.y * 128, bn = blockIdx.x * 128;

    int ldr = tid >> 1;
    int half = tid & 1;
    int ebase = half * 16;
    int c2base = half * 8;

    const __nv_bfloat16* Ag = A  + (size_t)(bm + ldr) * GK + ebase;
    const __nv_bfloat16* Bg = Bt + (size_t)(bn + ldr) * GK + ebase;

    uint32_t sAs = smem_u32(&As[0][0]);
    uint32_t sBs = smem_u32(&Bs[0][0]);
    uint32_t soff = (uint32_t)(ldr * ROWP32 + c2base) * 4;

    uint32_t a_off = (uint32_t)((wr * 64 + (lane & 15)) * 80 + ((lane >> 4) & 1) * 16);
    uint32_t b_off = (uint32_t)((wc * 32 + (lane & 7) + ((lane >> 4) & 1) * 8) * 80
                                + ((lane >> 3) & 1) * 16);

    float acc[4][4][4];
#pragma unroll
    for (int i = 0; i < 4; i++)
#pragma unroll
        for (int j = 0; j < 4; j++)
#pragma unroll
            for (int k = 0; k < 4; k++) acc[i][j][k] = 0.f;

#pragma unroll
    for (int s = 0; s < 2; s++) {
        int kc = s * 32;
        uint32_t ab = sAs + s * (STAGE_U * 4) + soff;
        uint32_t bb = sBs + s * (STAGE_U * 4) + soff;
        cp16(ab,      Ag + kc);
        cp16(ab + 16, Ag + kc + 8);
        cp16(bb,      Bg + kc);
        cp16(bb + 16, Bg + kc + 8);
        CP_COMMIT();
    }

    for (int it = 0; it < KCHUNKS; it++) {
        CP_WAIT1();
        __syncthreads();
        if (it + 2 < KCHUNKS) {
            int s = (it + 2) % NSTG;
            int kc = (it + 2) * 32;
            uint32_t ab = sAs + s * (STAGE_U * 4) + soff;
            uint32_t bb = sBs + s * (STAGE_U * 4) + soff;
            cp16(ab,      Ag + kc);
            cp16(ab + 16, Ag + kc + 8);
            cp16(bb,      Bg + kc);
            cp16(bb + 16, Bg + kc + 8);
        }
        CP_COMMIT();

        uint32_t aS = sAs + (it % NSTG) * (STAGE_U * 4) + a_off;
        uint32_t bS = sBs + (it % NSTG) * (STAGE_U * 4) + b_off;
#pragma unroll
        for (int ks = 0; ks < 2; ks++) {
            uint32_t af[4][4], bf[4][2];
#pragma unroll
            for (int mt = 0; mt < 4; mt++)
                ldsm_x4(af[mt], aS + mt * (16 * 80) + ks * 32);
#pragma unroll
            for (int j = 0; j < 2; j++)
                ldsm_x4(&bf[2 * j][0], bS + j * (16 * 80) + ks * 32);
#pragma unroll
            for (int mt = 0; mt < 4; mt++)
#pragma unroll
                for (int nt = 0; nt < 4; nt++)
                    mma_bf16(acc[mt][nt], af[mt], bf[nt]);
        }
    }

#pragma unroll
    for (int mt = 0; mt < 4; mt++) {
        size_t r0 = (size_t)(bm + wr * 64 + mt * 16 + lg);
#pragma unroll
        for (int nt = 0; nt < 4; nt++) {
            int c0 = bn + wc * 32 + nt * 8 + lk * 2;
            float bx = bias[c0], by = bias[c0 + 1];
            float v00 = acc[mt][nt][0] + bx, v01 = acc[mt][nt][1] + by;
            float v10 = acc[mt][nt][2] + bx, v11 = acc[mt][nt][3] + by;
            if (obf) {
                *(uint32_t*)(C16 + r0 * N + c0)       = packbf(v00, v01);
                *(uint32_t*)(C16 + (r0 + 8) * N + c0) = packbf(v10, v11);
            } else {
                *(float2*)(C + r0 * N + c0)       = make_float2(v00, v01);
                *(float2*)(C + (r0 + 8) * N + c0) = make_float2(v10, v11);
            }
        }
    }
}

// ---------------- temporal attention, S=16 (bf16 qkv input) ----------------
__global__ __launch_bounds__(256) void attn16_kernel(
    const __nv_bfloat16* __restrict__ qkv, __nv_bfloat16* __restrict__ out)
{
    __shared__ __align__(16) float Qs[16][68];
    __shared__ __align__(16) float Ks[16][68];
    __shared__ __align__(16) float Vs[16][64];
    __shared__ float Ps[16][17];

    int h = blockIdx.y;
    int seq = blockIdx.x;
    int b = seq / Pp, p = seq % Pp;
    int base = b * Ff * Pp + p;
    int tid = threadIdx.x;

    {
        int f = tid >> 4, d4 = (tid & 15) * 4;
        const __nv_bfloat16* row = qkv + (size_t)(base + f * Pp) * QKVW + h * HD + d4;
        uint2 qu = *(const uint2*)(row);
        uint2 ku = *(const uint2*)(row + Dd);
        uint2 vu = *(const uint2*)(row + 2 * Dd);
        float2 qa = ubf2(qu.x), qb = ubf2(qu.y);
        float2 ka = ubf2(ku.x), kb = ubf2(ku.y);
        float2 va = ubf2(vu.x), vb = ubf2(vu.y);
        *(float4*)(&Qs[f][d4]) = make_float4(qa.x, qa.y, qb.x, qb.y);
        *(float4*)(&Ks[f][d4]) = make_float4(ka.x, ka.y, kb.x, kb.y);
        *(float4*)(&Vs[f][d4]) = make_float4(va.x, va.y, vb.x, vb.y);
    }
    __syncthreads();

    {
        int q = tid >> 4, k = tid & 15;
        float acc = 0.f;
#pragma unroll
        for (int d4 = 0; d4 < 16; d4++) {
            float4 kv = *(const float4*)(&Ks[k][d4 * 4]);
            float4 qv = *(const float4*)(&Qs[q][d4 * 4]);
            acc += qv.x * kv.x + qv.y * kv.y + qv.z * kv.z + qv.w * kv.w;
        }
        acc *= 0.125f;
        float m = acc;
#pragma unroll
        for (int o = 8; o; o >>= 1) m = fmaxf(m, __shfl_xor_sync(0xffffffffu, m, o));
        float e = __expf(acc - m);
        float s = e;
#pragma unroll
        for (int o = 8; o; o >>= 1) s += __shfl_xor_sync(0xffffffffu, s, o);
        Ps[q][k] = e / s;
    }
    __syncthreads();

    {
        int d = tid & 63;
        int q0 = (tid >> 6) * 4;
        float a0 = 0.f, a1 = 0.f, a2 = 0.f, a3 = 0.f;
#pragma unroll
        for (int k = 0; k < 16; k++) {
            float v = Vs[k][d];
            a0 += Ps[q0 + 0][k] * v;
            a1 += Ps[q0 + 1][k] * v;
            a2 += Ps[q0 + 2][k] * v;
            a3 += Ps[q0 + 3][k] * v;
        }
        size_t o0 = (size_t)(base + (q0 + 0) * Pp) * Dd + h * HD + d;
        out[o0]                       = __float2bfloat16(a0);
        out[o0 + (size_t)Pp * Dd]     = __float2bfloat16(a1);
        out[o0 + (size_t)2 * Pp * Dd] = __float2bfloat16(a2);
        out[o0 + (size_t)3 * Pp * Dd] = __float2bfloat16(a3);
    }
}

// ---------------- spatial attention, S=196 padded to 208, bf16 MMA ----------
// Smem: Qu + Ku + Tu only (85.5 KB) -> 2 CTAs/SM. V is staged TRANSPOSED
// directly from gmem (coalesced: d fast-varying within a qkv row).
#define SPAD 208
#define QRU 36
#define VTR 108
__global__ __launch_bounds__(256, 2) void attn196_kernel(
    const __nv_bfloat16* __restrict__ qkv, __nv_bfloat16* __restrict__ out)
{
    extern __shared__ __align__(16) uint32_t sm196[];
    uint32_t* Qu = sm196;                 // [208][36]
    uint32_t* Ku = Qu + SPAD * QRU;       // [208][36]
    uint32_t* Tu = Ku + SPAD * QRU;       // Vt: [64][108]

    int h = blockIdx.y;
    int base = blockIdx.x * Pp;
    int tid = threadIdx.x;
    int wid = tid >> 5, lane = tid & 31;
    int lg = lane >> 2, lk = lane & 3;

    const uint16_t* qkvu = (const uint16_t*)qkv;

    // stage Q, K (u32 copies; rows >= 196 zeroed)
    for (int i = tid; i < SPAD * 16; i += 256) {
        int s = i >> 4, d4 = (i & 15) * 2;
        uint32_t q0 = 0, q1 = 0, k0 = 0, k1 = 0;
        if (s < Pp) {
            const __nv_bfloat16* row = qkv + (size_t)(base + s) * QKVW + h * HD + d4 * 2;
            uint2 qq = *(const uint2*)(row);
            uint2 kk = *(const uint2*)(row + Dd);
            q0 = qq.x; q1 = qq.y;
            k0 = kk.x; k1 = kk.y;
        }
        Qu[s * QRU + d4] = q0; Qu[s * QRU + d4 + 1] = q1;
        Ku[s * QRU + d4] = k0; Ku[s * QRU + d4 + 1] = k1;
    }
    // stage V transposed, directly from gmem (coalesced along d)
    for (int i = tid; i < 64 * 104; i += 256) {
        int d = i & 63, s2 = i >> 6;
        int r0 = 2 * s2, r1 = 2 * s2 + 1;
        uint32_t lo = 0, hi = 0;
        if (r0 < Pp)
            lo = qkvu[(size_t)(base + r0) * QKVW + 2 * Dd + h * HD + d];
        if (r1 < Pp)
            hi = qkvu[(size_t)(base + r1) * QKVW + 2 * Dd + h * HD + d];
        Tu[d * VTR + s2] = lo | (hi << 16);
    }
    __syncthreads();

    for (int mt = wid; mt < 13; mt += 8) {
        int r = mt * 16 + lg;

        uint32_t qa[4][4];
#pragma unroll
        for (int kc = 0; kc < 4; kc++) {
            int c2 = kc * 8 + lk;
            qa[kc][0] = Qu[r * QRU + c2];
            qa[kc][1] = Qu[(r + 8) * QRU + c2];
            qa[kc][2] = Qu[r * QRU + c2 + 4];
            qa[kc][3] = Qu[(r + 8) * QRU + c2 + 4];
        }

        float sc[26][4];
#pragma unroll
        for (int nt = 0; nt < 26; nt++)
            sc[nt][0] = sc[nt][1] = sc[nt][2] = sc[nt][3] = 0.f;
#pragma unroll
        for (int nt = 0; nt < 26; nt++) {
            int n = nt * 8 + lg;
#pragma unroll
            for (int kc = 0; kc < 4; kc++) {
                uint32_t b[2];
                b[0] = Ku[n * QRU + kc * 8 + lk];
                b[1] = Ku[n * QRU + kc * 8 + lk + 4];
                mma_bf16(sc[nt], qa[kc], b);
            }
        }

#pragma unroll
        for (int nt = 0; nt < 26; nt++) {
            int col0 = nt * 8 + 2 * lk;
            sc[nt][0] = (col0     < Pp) ? sc[nt][0] * 0.125f : -1e30f;
            sc[nt][1] = (col0 + 1 < Pp) ? sc[nt][1] * 0.125f : -1e30f;
            sc[nt][2] = (col0     < Pp) ? sc[nt][2] * 0.125f : -1e30f;
            sc[nt][3] = (col0 + 1 < Pp) ? sc[nt][3] * 0.125f : -1e30f;
        }

        float m0 = -1e30f, m1 = -1e30f;
#pragma unroll
        for (int nt = 0; nt < 26; nt++) {
            m0 = fmaxf(m0, fmaxf(sc[nt][0], sc[nt][1]));
            m1 = fmaxf(m1, fmaxf(sc[nt][2], sc[nt][3]));
        }
        m0 = fmaxf(m0, __shfl_xor_sync(0xffffffffu, m0, 1));
        m0 = fmaxf(m0, __shfl_xor_sync(0xffffffffu, m0, 2));
        m1 = fmaxf(m1, __shfl_xor_sync(0xffffffffu, m1, 1));
        m1 = fmaxf(m1, __shfl_xor_sync(0xffffffffu, m1, 2));

        float s0 = 0.f, s1 = 0.f;
#pragma unroll
        for (int nt = 0; nt < 26; nt++) {
            sc[nt][0] = __expf(sc[nt][0] - m0); s0 += sc[nt][0];
            sc[nt][1] = __expf(sc[nt][1] - m0); s0 += sc[nt][1];
            sc[nt][2] = __expf(sc[nt][2] - m1); s1 += sc[nt][2];
            sc[nt][3] = __expf(sc[nt][3] - m1); s1 += sc[nt][3];
        }
        s0 += __shfl_xor_sync(0xffffffffu, s0, 1);
        s0 += __shfl_xor_sync(0xffffffffu, s0, 2);
        s1 += __shfl_xor_sync(0xffffffffu, s1, 1);
        s1 += __shfl_xor_sync(0xffffffffu, s1, 2);

        uint32_t pk[13][4];
#pragma unroll
        for (int j = 0; j < 13; j++) {
            pk[j][0] = packbf(sc[2 * j][0],     sc[2 * j][1]);
            pk[j][1] = packbf(sc[2 * j][2],     sc[2 * j][3]);
            pk[j][2] = packbf(sc[2 * j + 1][0], sc[2 * j + 1][1]);
            pk[j][3] = packbf(sc[2 * j + 1][2], sc[2 * j + 1][3]);
        }

        float oa[8][4];
#pragma unroll
        for (int nd = 0; nd < 8; nd++)
            oa[nd][0] = oa[nd][1] = oa[nd][2] = oa[nd][3] = 0.f;
#pragma unroll
        for (int j = 0; j < 13; j++) {
#pragma unroll
            for (int nd = 0; nd < 8; nd++) {
                int n = nd * 8 + lg;
                uint32_t b[2];
                b[0] = Tu[n * VTR + j * 8 + lk];
                b[1] = Tu[n * VTR + j * 8 + lk + 4];
                mma_bf16(oa[nd], pk[j], b);
            }
        }

        float inv0 = 1.0f / s0, inv1 = 1.0f / s1;
        int row0 = r, row1 = r + 8;
#pragma unroll
        for (int nd = 0; nd < 8; nd++) {
            int col = nd * 8 + 2 * lk;
            if (row0 < Pp) {
                uint32_t u = packbf(oa[nd][0] * inv0, oa[nd][1] * inv0);
                *(uint32_t*)(out + (size_t)(base + row0) * Dd + h * HD + col) = u;
            }
            if (row1 < Pp) {
                uint32_t u = packbf(oa[nd][2] * inv1, oa[nd][3] * inv1);
                *(uint32_t*)(out + (size_t)(base + row1) * Dd + h * HD + col) = u;
            }
        }
    }
}

// ---------------- fused residual + LayerNorm (register-resident row) ---------
__global__ __launch_bounds__(256) void add_ln_kernel(
    const float* __restrict__ x, const float* __restrict__ y,
    const float* __restrict__ g, const float* __restrict__ b,
    float* __restrict__ out, __nv_bfloat16* __restrict__ outb, int wb)
{
    __shared__ float ps[8], ps2[8];
    __shared__ float red[2];

    size_t row = blockIdx.x;
    const float* xr = x + row * Dd;
    const float* yr = y + row * Dd;
    int tid = threadIdx.x;
    int lane = tid & 31, wid = tid >> 5;

    float v[3];
    float s = 0.f, s2 = 0.f;
#pragma unroll
    for (int k = 0; k < 3; k++) {
        int d = tid + k * 256;
        v[k] = xr[d] + yr[d];
        s += v[k];
        s2 += v[k] * v[k];
    }
#pragma unroll
    for (int o = 16; o; o >>= 1) {
        s  += __shfl_xor_sync(0xffffffffu, s, o);
        s2 += __shfl_xor_sync(0xffffffffu, s2, o);
    }
    if (lane == 0) { ps[wid] = s; ps2[wid] = s2; }
    __syncthreads();
    if (tid < 8) {
        s = ps[tid]; s2 = ps2[tid];
#pragma unroll
        for (int o = 4; o; o >>= 1) {
            s  += __shfl_xor_sync(0xffu, s, o);
            s2 += __shfl_xor_sync(0xffu, s2, o);
        }
        if (tid == 0) {
            float mean = s / Dd;
            float var = s2 / Dd - mean * mean;
            red[0] = mean;
            red[1] = rsqrtf(var + 1e-5f);
        }
    }
    __syncthreads();
    float mean = red[0], rstd = red[1];
#pragma unroll
    for (int k = 0; k < 3; k++) {
        int d = tid + k * 256;
        float o = (v[k] - mean) * rstd * g[d] + b[d];
        out[row * Dd + d] = o;
        if (wb) outb[row * Dd + d] = __float2bfloat16(o);
    }
}

// ---------------- launch ----------------
extern "C" void kernel_launch(void* const* d_in, const int* in_sizes, int n_in,
                              void* d_out, int out_size)
{
    const float* x      = (const float*)d_in[0];
    const float* Wqkv_t = (const float*)d_in[1];
    const float* bqkv_t = (const float*)d_in[2];
    const float* Wo_t   = (const float*)d_in[3];
    const float* bo_t   = (const float*)d_in[4];
    const float* Wqkv_s = (const float*)d_in[5];
    const float* bqkv_s = (const float*)d_in[6];
    const float* Wo_s   = (const float*)d_in[7];
    const float* bo_s   = (const float*)d_in[8];
    const float* g1     = (const float*)d_in[9];
    const float* b1     = (const float*)d_in[10];
    const float* g2     = (const float*)d_in[11];
    const float* b2     = (const float*)d_in[12];
    float* out = (float*)d_out;

    float *y, *x1;
    __nv_bfloat16 *qkvb, *xb, *x1b, *attnb, *wtb;
    cudaGetSymbolAddress((void**)&qkvb,  g_qkvb);
    cudaGetSymbolAddress((void**)&y,     g_y);
    cudaGetSymbolAddress((void**)&x1,    g_x1);
    cudaGetSymbolAddress((void**)&xb,    g_xb);
    cudaGetSymbolAddress((void**)&x1b,   g_x1b);
    cudaGetSymbolAddress((void**)&attnb, g_attnb);
    cudaGetSymbolAddress((void**)&wtb,   g_wtb);

    const int SMEM196 = (2 * SPAD * QRU + 64 * VTR) * (int)sizeof(uint32_t);  // 87552
    cudaFuncSetAttribute(attn196_kernel, cudaFuncAttributeMaxDynamicSharedMemorySize, SMEM196);

    dim3 tb(32, 8);
    dim3 tg_qkv(QKVW / 32, GK / 32);      // (72, 24)
    dim3 tg_out(Dd / 32, GK / 32);        // (24, 24)
    dim3 gg_qkv(QKVW / 128, NTOK / 128);  // (18, 196)
    dim3 gg_out(Dd / 128, NTOK / 128);    // (6, 196)
    int n4 = NTOK * Dd / 4;

    // x -> bf16
    f2b_kernel<<<(n4 + 255) / 256, 256>>>(x, xb, n4);
    // temporal QKV projection -> bf16 qkv
    transpose_b<<<tg_qkv, tb>>>(Wqkv_t, wtb, GK, QKVW);
    gemm_mma<<<gg_qkv, 256>>>(xb, wtb, bqkv_t, nullptr, qkvb, QKVW, 1);
    // temporal attention (S=16)
    attn16_kernel<<<dim3(Bb * Pp, Hh), 256>>>(qkvb, attnb);
    // temporal out-projection -> f32 y
    transpose_b<<<tg_out, tb>>>(Wo_t, wtb, GK, Dd);
    gemm_mma<<<gg_out, 256>>>(attnb, wtb, bo_t, y, nullptr, Dd, 0);
    // x1 = LN(x + y)  (+ bf16 copy)
    add_ln_kernel<<<NTOK, 256>>>(x, y, g1, b1, x1, x1b, 1);
    // spatial QKV projection -> bf16 qkv
    transpose_b<<<tg_qkv, tb>>>(Wqkv_s, wtb, GK, QKVW);
    gemm_mma<<<gg_qkv, 256>>>(x1b, wtb, bqkv_s, nullptr, qkvb, QKVW, 1);
    // spatial attention (S=196), 2 CTAs/SM
    attn196_kernel<<<dim3(Bb * Ff, Hh), 256, SMEM196>>>(qkvb, attnb);
    // spatial out-projection -> f32 y
    transpose_b<<<tg_out, tb>>>(Wo_s, wtb, GK, Dd);
    gemm_mma<<<gg_out, 256>>>(attnb, wtb, bo_s, y, nullptr, Dd, 0);
    // out = LN(x1 + y)
    add_ln_kernel<<<NTOK, 256>>>(x1, y, g2, b2, out, (__nv_bfloat16*)nullptr, 0);
}

// round 16
// speedup vs baseline: 1.4029x; 1.0399x over previous
#include <cuda_runtime.h>
#include <cuda_bf16.h>
#include <cstdint>

#define Bb 8
#define Ff 16
#define Pp 196
#define Dd 768
#define Hh 12
#define HD 64
#define NTOK (Bb*Ff*Pp)          // 25088
#define QKVW (3*Dd)              // 2304
#define GK 768                   // K for all GEMMs
#define KCHUNKS (GK/32)          // 24

// ---------------- scratch (allocation-free: __device__ globals) ----------------
__device__ __nv_bfloat16 g_qkvb[(size_t)NTOK * QKVW];  // 115 MB (bf16 qkv)
__device__ float         g_y[(size_t)NTOK * Dd];       // 77 MB
__device__ float         g_x1[(size_t)NTOK * Dd];      // 77 MB
__device__ __nv_bfloat16 g_xb[(size_t)NTOK * Dd];      // 38.5 MB
__device__ __nv_bfloat16 g_x1b[(size_t)NTOK * Dd];     // 38.5 MB
__device__ __nv_bfloat16 g_attnb[(size_t)NTOK * Dd];   // 38.5 MB
__device__ __nv_bfloat16 g_wtb[(size_t)Dd * QKVW];     // 3.5 MB

__device__ __forceinline__ void mma_bf16(float* c, const uint32_t* a, const uint32_t* b) {
    asm volatile(
        "mma.sync.aligned.m16n8k16.row.col.f32.bf16.bf16.f32 "
        "{%0,%1,%2,%3}, {%4,%5,%6,%7}, {%8,%9}, {%0,%1,%2,%3};"
        : "+f"(c[0]), "+f"(c[1]), "+f"(c[2]), "+f"(c[3])
        : "r"(a[0]), "r"(a[1]), "r"(a[2]), "r"(a[3]), "r"(b[0]), "r"(b[1]));
}
__device__ __forceinline__ void ldsm_x4(uint32_t* r, uint32_t addr) {
    asm volatile("ldmatrix.sync.aligned.m8n8.x4.shared.b16 {%0,%1,%2,%3}, [%4];"
        : "=r"(r[0]), "=r"(r[1]), "=r"(r[2]), "=r"(r[3]) : "r"(addr));
}
__device__ __forceinline__ uint32_t smem_u32(const void* p) {
    uint32_t a;
    asm("{ .reg .u64 t; cvta.to.shared.u64 t, %1; cvt.u32.u64 %0, t; }" : "=r"(a) : "l"(p));
    return a;
}
__device__ __forceinline__ void cp16(uint32_t dst, const void* src) {
    asm volatile("cp.async.cg.shared.global [%0], [%1], 16;" :: "r"(dst), "l"(src));
}
#define CP_COMMIT() asm volatile("cp.async.commit_group;" ::: "memory")
#define CP_WAIT1()  asm volatile("cp.async.wait_group 1;" ::: "memory")

__device__ __forceinline__ uint32_t packbf(float lo, float hi) {
    __nv_bfloat162 p = __float22bfloat162_rn(make_float2(lo, hi));
    return *reinterpret_cast<uint32_t*>(&p);
}

// ---------------- f32 -> bf16 convert ----------------
__global__ __launch_bounds__(256) void f2b_kernel(
    const float* __restrict__ in, __nv_bfloat16* __restrict__ out, int n4)
{
    int i = blockIdx.x * 256 + threadIdx.x;
    if (i < n4) {
        float4 v = *(const float4*)(in + (size_t)i * 4);
        uint2 u;
        u.x = packbf(v.x, v.y);
        u.y = packbf(v.z, v.w);
        *(uint2*)(out + (size_t)i * 4) = u;
    }
}

// ---------------- weight transpose to bf16: out[N,K] = bf16(in[K,N]) ----------
__global__ __launch_bounds__(256) void transpose_b(
    const float* __restrict__ in, __nv_bfloat16* __restrict__ out, int K, int N)
{
    __shared__ float t[32][33];
    int n0 = blockIdx.x * 32, k0 = blockIdx.y * 32;
    int tx = threadIdx.x, ty = threadIdx.y;   // 32 x 8
#pragma unroll
    for (int j = 0; j < 32; j += 8)
        t[ty + j][tx] = in[(size_t)(k0 + ty + j) * N + n0 + tx];
    __syncthreads();
#pragma unroll
    for (int j = 0; j < 32; j += 8)
        out[(size_t)(n0 + ty + j) * K + k0 + tx] = __float2bfloat16(t[tx][ty + j]);
}

// ---------------- BF16 mma.sync GEMM, cp.async + ldmatrix -------------------
#define ROWP32 20
#define STAGE_U (128 * ROWP32)
#define NSTG 3
__global__ __launch_bounds__(256, 2) void gemm_mma(
    const __nv_bfloat16* __restrict__ A, const __nv_bfloat16* __restrict__ Bt,
    const float* __restrict__ bias, float* __restrict__ C,
    __nv_bfloat16* __restrict__ C16, int N, int obf)
{
    __shared__ __align__(16) uint32_t As[NSTG][STAGE_U];
    __shared__ __align__(16) uint32_t Bs[NSTG][STAGE_U];

    int tid = threadIdx.x;
    int wid = tid >> 5, lane = tid & 31;
    int wr = wid >> 2, wc = wid & 3;
    int lg = lane >> 2, lk = lane & 3;
    int bm = blockIdx.y * 128, bn = blockIdx.x * 128;

    int ldr = tid >> 1;
    int half = tid & 1;
    int ebase = half * 16;
    int c2base = half * 8;

    const __nv_bfloat16* Ag = A  + (size_t)(bm + ldr) * GK + ebase;
    const __nv_bfloat16* Bg = Bt + (size_t)(bn + ldr) * GK + ebase;

    uint32_t sAs = smem_u32(&As[0][0]);
    uint32_t sBs = smem_u32(&Bs[0][0]);
    uint32_t soff = (uint32_t)(ldr * ROWP32 + c2base) * 4;

    uint32_t a_off = (uint32_t)((wr * 64 + (lane & 15)) * 80 + ((lane >> 4) & 1) * 16);
    uint32_t b_off = (uint32_t)((wc * 32 + (lane & 7) + ((lane >> 4) & 1) * 8) * 80
                                + ((lane >> 3) & 1) * 16);

    float acc[4][4][4];
#pragma unroll
    for (int i = 0; i < 4; i++)
#pragma unroll
        for (int j = 0; j < 4; j++)
#pragma unroll
            for (int k = 0; k < 4; k++) acc[i][j][k] = 0.f;

#pragma unroll
    for (int s = 0; s < 2; s++) {
        int kc = s * 32;
        uint32_t ab = sAs + s * (STAGE_U * 4) + soff;
        uint32_t bb = sBs + s * (STAGE_U * 4) + soff;
        cp16(ab,      Ag + kc);
        cp16(ab + 16, Ag + kc + 8);
        cp16(bb,      Bg + kc);
        cp16(bb + 16, Bg + kc + 8);
        CP_COMMIT();
    }

    for (int it = 0; it < KCHUNKS; it++) {
        CP_WAIT1();
        __syncthreads();
        if (it + 2 < KCHUNKS) {
            int s = (it + 2) % NSTG;
            int kc = (it + 2) * 32;
            uint32_t ab = sAs + s * (STAGE_U * 4) + soff;
            uint32_t bb = sBs + s * (STAGE_U * 4) + soff;
            cp16(ab,      Ag + kc);
            cp16(ab + 16, Ag + kc + 8);
            cp16(bb,      Bg + kc);
            cp16(bb + 16, Bg + kc + 8);
        }
        CP_COMMIT();

        uint32_t aS = sAs + (it % NSTG) * (STAGE_U * 4) + a_off;
        uint32_t bS = sBs + (it % NSTG) * (STAGE_U * 4) + b_off;
#pragma unroll
        for (int ks = 0; ks < 2; ks++) {
            uint32_t af[4][4], bf[4][2];
#pragma unroll
            for (int mt = 0; mt < 4; mt++)
                ldsm_x4(af[mt], aS + mt * (16 * 80) + ks * 32);
#pragma unroll
            for (int j = 0; j < 2; j++)
                ldsm_x4(&bf[2 * j][0], bS + j * (16 * 80) + ks * 32);
#pragma unroll
            for (int mt = 0; mt < 4; mt++)
#pragma unroll
                for (int nt = 0; nt < 4; nt++)
                    mma_bf16(acc[mt][nt], af[mt], bf[nt]);
        }
    }

#pragma unroll
    for (int mt = 0; mt < 4; mt++) {
        size_t r0 = (size_t)(bm + wr * 64 + mt * 16 + lg);
#pragma unroll
        for (int nt = 0; nt < 4; nt++) {
            int c0 = bn + wc * 32 + nt * 8 + lk * 2;
            float bx = bias[c0], by = bias[c0 + 1];
            float v00 = acc[mt][nt][0] + bx, v01 = acc[mt][nt][1] + by;
            float v10 = acc[mt][nt][2] + bx, v11 = acc[mt][nt][3] + by;
            if (obf) {
                *(uint32_t*)(C16 + r0 * N + c0)       = packbf(v00, v01);
                *(uint32_t*)(C16 + (r0 + 8) * N + c0) = packbf(v10, v11);
            } else {
                *(float2*)(C + r0 * N + c0)       = make_float2(v00, v01);
                *(float2*)(C + (r0 + 8) * N + c0) = make_float2(v10, v11);
            }
        }
    }
}

// ---------------- temporal attention, S=16: warp-per-(seq,head), MMA, no smem
// Fragments loaded directly from gmem (qkv rows are K-contiguous).
__global__ __launch_bounds__(256) void attn16_kernel(
    const __nv_bfloat16* __restrict__ qkv, __nv_bfloat16* __restrict__ out)
{
    int wid = threadIdx.x >> 5, lane = threadIdx.x & 31;
    int lg = lane >> 2, lk = lane & 3;
    int inst = blockIdx.x * 8 + wid;          // 0 .. 18815
    int h = inst % Hh;
    int seq = inst / Hh;
    int b = seq / Pp, p = seq % Pp;
    int base = b * Ff * Pp + p;               // + f*Pp per frame

    const uint16_t* qk = (const uint16_t*)qkv;
    const size_t RSTRIDE = (size_t)Pp * QKVW; // stride between frames

    // Q A-fragments: rows lg, lg+8; 4 k16 chunks
    uint32_t qa[4][4];
    {
        size_t r0 = (size_t)(base + lg * Pp) * QKVW + h * HD;
        size_t r1 = r0 + 8 * RSTRIDE;
#pragma unroll
        for (int kc = 0; kc < 4; kc++) {
            int k0 = kc * 16 + lk * 2;
            qa[kc][0] = *(const uint32_t*)(qk + r0 + k0);
            qa[kc][1] = *(const uint32_t*)(qk + r1 + k0);
            qa[kc][2] = *(const uint32_t*)(qk + r0 + k0 + 8);
            qa[kc][3] = *(const uint32_t*)(qk + r1 + k0 + 8);
        }
    }

    // scores: 2 n8 key-tiles
    float sc[2][4];
    sc[0][0] = sc[0][1] = sc[0][2] = sc[0][3] = 0.f;
    sc[1][0] = sc[1][1] = sc[1][2] = sc[1][3] = 0.f;
#pragma unroll
    for (int nt = 0; nt < 2; nt++) {
        size_t kr = (size_t)(base + (nt * 8 + lg) * Pp) * QKVW + Dd + h * HD;
#pragma unroll
        for (int kc = 0; kc < 4; kc++) {
            int k0 = kc * 16 + lk * 2;
            uint32_t bfr[2];
            bfr[0] = *(const uint32_t*)(qk + kr + k0);
            bfr[1] = *(const uint32_t*)(qk + kr + k0 + 8);
            mma_bf16(sc[nt], qa[kc], bfr);
        }
    }
#pragma unroll
    for (int nt = 0; nt < 2; nt++) {
        sc[nt][0] *= 0.125f; sc[nt][1] *= 0.125f;
        sc[nt][2] *= 0.125f; sc[nt][3] *= 0.125f;
    }

    // softmax: row lg -> regs {0,1}, row lg+8 -> regs {2,3}; quad shuffles
    float m0 = fmaxf(fmaxf(sc[0][0], sc[0][1]), fmaxf(sc[1][0], sc[1][1]));
    float m1 = fmaxf(fmaxf(sc[0][2], sc[0][3]), fmaxf(sc[1][2], sc[1][3]));
    m0 = fmaxf(m0, __shfl_xor_sync(0xffffffffu, m0, 1));
    m0 = fmaxf(m0, __shfl_xor_sync(0xffffffffu, m0, 2));
    m1 = fmaxf(m1, __shfl_xor_sync(0xffffffffu, m1, 1));
    m1 = fmaxf(m1, __shfl_xor_sync(0xffffffffu, m1, 2));
    float s0 = 0.f, s1 = 0.f;
#pragma unroll
    for (int nt = 0; nt < 2; nt++) {
        sc[nt][0] = __expf(sc[nt][0] - m0); s0 += sc[nt][0];
        sc[nt][1] = __expf(sc[nt][1] - m0); s0 += sc[nt][1];
        sc[nt][2] = __expf(sc[nt][2] - m1); s1 += sc[nt][2];
        sc[nt][3] = __expf(sc[nt][3] - m1); s1 += sc[nt][3];
    }
    s0 += __shfl_xor_sync(0xffffffffu, s0, 1);
    s0 += __shfl_xor_sync(0xffffffffu, s0, 2);
    s1 += __shfl_xor_sync(0xffffffffu, s1, 1);
    s1 += __shfl_xor_sync(0xffffffffu, s1, 2);

    // P as A-fragment (C-layout == A-layout; keys are the k dim)
    uint32_t pa[4];
    pa[0] = packbf(sc[0][0], sc[0][1]);
    pa[1] = packbf(sc[0][2], sc[0][3]);
    pa[2] = packbf(sc[1][0], sc[1][1]);
    pa[3] = packbf(sc[1][2], sc[1][3]);

    // PV: B-fragment = V^T; lane needs V[key=2lk(+1)][d=n] and keys +8
    size_t v0r = (size_t)(base + (2 * lk) * Pp)     * QKVW + 2 * Dd + h * HD;
    size_t v1r = v0r + RSTRIDE;
    size_t v2r = v0r + 8 * RSTRIDE;
    size_t v3r = v0r + 9 * RSTRIDE;

    float oa[8][4];
#pragma unroll
    for (int nd = 0; nd < 8; nd++)
        oa[nd][0] = oa[nd][1] = oa[nd][2] = oa[nd][3] = 0.f;
#pragma unroll
    for (int nd = 0; nd < 8; nd++) {
        int n = nd * 8 + lg;
        uint32_t bb[2];
        bb[0] = (uint32_t)qk[v0r + n] | ((uint32_t)qk[v1r + n] << 16);
        bb[1] = (uint32_t)qk[v2r + n] | ((uint32_t)qk[v3r + n] << 16);
        mma_bf16(oa[nd], pa, bb);
    }

    // normalize + store
    float inv0 = 1.0f / s0, inv1 = 1.0f / s1;
    size_t o0 = (size_t)(base + lg * Pp) * Dd + h * HD;
    size_t o1 = (size_t)(base + (lg + 8) * Pp) * Dd + h * HD;
#pragma unroll
    for (int nd = 0; nd < 8; nd++) {
        int col = nd * 8 + lk * 2;
        *(uint32_t*)(out + o0 + col) = packbf(oa[nd][0] * inv0, oa[nd][1] * inv0);
        *(uint32_t*)(out + o1 + col) = packbf(oa[nd][2] * inv1, oa[nd][3] * inv1);
    }
}

// ---------------- spatial attention, S=196 padded to 208, bf16 MMA ----------
#define SPAD 208
#define QRU 36
#define VTR 108
__global__ __launch_bounds__(256, 2) void attn196_kernel(
    const __nv_bfloat16* __restrict__ qkv, __nv_bfloat16* __restrict__ out)
{
    extern __shared__ __align__(16) uint32_t sm196[];
    uint32_t* Qu = sm196;                 // [208][36]
    uint32_t* Ku = Qu + SPAD * QRU;       // [208][36]
    uint32_t* Tu = Ku + SPAD * QRU;       // Vt: [64][108]

    int h = blockIdx.y;
    int base = blockIdx.x * Pp;
    int tid = threadIdx.x;
    int wid = tid >> 5, lane = tid & 31;
    int lg = lane >> 2, lk = lane & 3;

    const uint16_t* qkvu = (const uint16_t*)qkv;

    for (int i = tid; i < SPAD * 16; i += 256) {
        int s = i >> 4, d4 = (i & 15) * 2;
        uint32_t q0 = 0, q1 = 0, k0 = 0, k1 = 0;
        if (s < Pp) {
            const __nv_bfloat16* row = qkv + (size_t)(base + s) * QKVW + h * HD + d4 * 2;
            uint2 qq = *(const uint2*)(row);
            uint2 kk = *(const uint2*)(row + Dd);
            q0 = qq.x; q1 = qq.y;
            k0 = kk.x; k1 = kk.y;
        }
        Qu[s * QRU + d4] = q0; Qu[s * QRU + d4 + 1] = q1;
        Ku[s * QRU + d4] = k0; Ku[s * QRU + d4 + 1] = k1;
    }
    for (int i = tid; i < 64 * 104; i += 256) {
        int d = i & 63, s2 = i >> 6;
        int r0 = 2 * s2, r1 = 2 * s2 + 1;
        uint32_t lo = 0, hi = 0;
        if (r0 < Pp)
            lo = qkvu[(size_t)(base + r0) * QKVW + 2 * Dd + h * HD + d];
        if (r1 < Pp)
            hi = qkvu[(size_t)(base + r1) * QKVW + 2 * Dd + h * HD + d];
        Tu[d * VTR + s2] = lo | (hi << 16);
    }
    __syncthreads();

    for (int mt = wid; mt < 13; mt += 8) {
        int r = mt * 16 + lg;

        uint32_t qa[4][4];
#pragma unroll
        for (int kc = 0; kc < 4; kc++) {
            int c2 = kc * 8 + lk;
            qa[kc][0] = Qu[r * QRU + c2];
            qa[kc][1] = Qu[(r + 8) * QRU + c2];
            qa[kc][2] = Qu[r * QRU + c2 + 4];
            qa[kc][3] = Qu[(r + 8) * QRU + c2 + 4];
        }

        float sc[26][4];
#pragma unroll
        for (int nt = 0; nt < 26; nt++)
            sc[nt][0] = sc[nt][1] = sc[nt][2] = sc[nt][3] = 0.f;
#pragma unroll
        for (int nt = 0; nt < 26; nt++) {
            int n = nt * 8 + lg;
#pragma unroll
            for (int kc = 0; kc < 4; kc++) {
                uint32_t b[2];
                b[0] = Ku[n * QRU + kc * 8 + lk];
                b[1] = Ku[n * QRU + kc * 8 + lk + 4];
                mma_bf16(sc[nt], qa[kc], b);
            }
        }

#pragma unroll
        for (int nt = 0; nt < 26; nt++) {
            int col0 = nt * 8 + 2 * lk;
            sc[nt][0] = (col0     < Pp) ? sc[nt][0] * 0.125f : -1e30f;
            sc[nt][1] = (col0 + 1 < Pp) ? sc[nt][1] * 0.125f : -1e30f;
            sc[nt][2] = (col0     < Pp) ? sc[nt][2] * 0.125f : -1e30f;
            sc[nt][3] = (col0 + 1 < Pp) ? sc[nt][3] * 0.125f : -1e30f;
        }

        float m0 = -1e30f, m1 = -1e30f;
#pragma unroll
        for (int nt = 0; nt < 26; nt++) {
            m0 = fmaxf(m0, fmaxf(sc[nt][0], sc[nt][1]));
            m1 = fmaxf(m1, fmaxf(sc[nt][2], sc[nt][3]));
        }
        m0 = fmaxf(m0, __shfl_xor_sync(0xffffffffu, m0, 1));
        m0 = fmaxf(m0, __shfl_xor_sync(0xffffffffu, m0, 2));
        m1 = fmaxf(m1, __shfl_xor_sync(0xffffffffu, m1, 1));
        m1 = fmaxf(m1, __shfl_xor_sync(0xffffffffu, m1, 2));

        float s0 = 0.f, s1 = 0.f;
#pragma unroll
        for (int nt = 0; nt < 26; nt++) {
            sc[nt][0] = __expf(sc[nt][0] - m0); s0 += sc[nt][0];
            sc[nt][1] = __expf(sc[nt][1] - m0); s0 += sc[nt][1];
            sc[nt][2] = __expf(sc[nt][2] - m1); s1 += sc[nt][2];
            sc[nt][3] = __expf(sc[nt][3] - m1); s1 += sc[nt][3];
        }
        s0 += __shfl_xor_sync(0xffffffffu, s0, 1);
        s0 += __shfl_xor_sync(0xffffffffu, s0, 2);
        s1 += __shfl_xor_sync(0xffffffffu, s1, 1);
        s1 += __shfl_xor_sync(0xffffffffu, s1, 2);

        uint32_t pk[13][4];
#pragma unroll
        for (int j = 0; j < 13; j++) {
            pk[j][0] = packbf(sc[2 * j][0],     sc[2 * j][1]);
            pk[j][1] = packbf(sc[2 * j][2],     sc[2 * j][3]);
            pk[j][2] = packbf(sc[2 * j + 1][0], sc[2 * j + 1][1]);
            pk[j][3] = packbf(sc[2 * j + 1][2], sc[2 * j + 1][3]);
        }

        float oa[8][4];
#pragma unroll
        for (int nd = 0; nd < 8; nd++)
            oa[nd][0] = oa[nd][1] = oa[nd][2] = oa[nd][3] = 0.f;
#pragma unroll
        for (int j = 0; j < 13; j++) {
#pragma unroll
            for (int nd = 0; nd < 8; nd++) {
                int n = nd * 8 + lg;
                uint32_t b[2];
                b[0] = Tu[n * VTR + j * 8 + lk];
                b[1] = Tu[n * VTR + j * 8 + lk + 4];
                mma_bf16(oa[nd], pk[j], b);
            }
        }

        float inv0 = 1.0f / s0, inv1 = 1.0f / s1;
        int row0 = r, row1 = r + 8;
#pragma unroll
        for (int nd = 0; nd < 8; nd++) {
            int col = nd * 8 + 2 * lk;
            if (row0 < Pp) {
                uint32_t u = packbf(oa[nd][0] * inv0, oa[nd][1] * inv0);
                *(uint32_t*)(out + (size_t)(base + row0) * Dd + h * HD + col) = u;
            }
            if (row1 < Pp) {
                uint32_t u = packbf(oa[nd][2] * inv1, oa[nd][3] * inv1);
                *(uint32_t*)(out + (size_t)(base + row1) * Dd + h * HD + col) = u;
            }
        }
    }
}

// ---------------- fused residual + LayerNorm (register-resident row) ---------
__global__ __launch_bounds__(256) void add_ln_kernel(
    const float* __restrict__ x, const float* __restrict__ y,
    const float* __restrict__ g, const float* __restrict__ b,
    float* __restrict__ out, __nv_bfloat16* __restrict__ outb, int wb)
{
    __shared__ float ps[8], ps2[8];
    __shared__ float red[2];

    size_t row = blockIdx.x;
    const float* xr = x + row * Dd;
    const float* yr = y + row * Dd;
    int tid = threadIdx.x;
    int lane = tid & 31, wid = tid >> 5;

    float v[3];
    float s = 0.f, s2 = 0.f;
#pragma unroll
    for (int k = 0; k < 3; k++) {
        int d = tid + k * 256;
        v[k] = xr[d] + yr[d];
        s += v[k];
        s2 += v[k] * v[k];
    }
#pragma unroll
    for (int o = 16; o; o >>= 1) {
        s  += __shfl_xor_sync(0xffffffffu, s, o);
        s2 += __shfl_xor_sync(0xffffffffu, s2, o);
    }
    if (lane == 0) { ps[wid] = s; ps2[wid] = s2; }
    __syncthreads();
    if (tid < 8) {
        s = ps[tid]; s2 = ps2[tid];
#pragma unroll
        for (int o = 4; o; o >>= 1) {
            s  += __shfl_xor_sync(0xffu, s, o);
            s2 += __shfl_xor_sync(0xffu, s2, o);
        }
        if (tid == 0) {
            float mean = s / Dd;
            float var = s2 / Dd - mean * mean;
            red[0] = mean;
            red[1] = rsqrtf(var + 1e-5f);
        }
    }
    __syncthreads();
    float mean = red[0], rstd = red[1];
#pragma unroll
    for (int k = 0; k < 3; k++) {
        int d = tid + k * 256;
        float o = (v[k] - mean) * rstd * g[d] + b[d];
        out[row * Dd + d] = o;
        if (wb) outb[row * Dd + d] = __float2bfloat16(o);
    }
}

// ---------------- launch ----------------
extern "C" void kernel_launch(void* const* d_in, const int* in_sizes, int n_in,
                              void* d_out, int out_size)
{
    const float* x      = (const float*)d_in[0];
    const float* Wqkv_t = (const float*)d_in[1];
    const float* bqkv_t = (const float*)d_in[2];
    const float* Wo_t   = (const float*)d_in[3];
    const float* bo_t   = (const float*)d_in[4];
    const float* Wqkv_s = (const float*)d_in[5];
    const float* bqkv_s = (const float*)d_in[6];
    const float* Wo_s   = (const float*)d_in[7];
    const float* bo_s   = (const float*)d_in[8];
    const float* g1     = (const float*)d_in[9];
    const float* b1     = (const float*)d_in[10];
    const float* g2     = (const float*)d_in[11];
    const float* b2     = (const float*)d_in[12];
    float* out = (float*)d_out;

    float *y, *x1;
    __nv_bfloat16 *qkvb, *xb, *x1b, *attnb, *wtb;
    cudaGetSymbolAddress((void**)&qkvb,  g_qkvb);
    cudaGetSymbolAddress((void**)&y,     g_y);
    cudaGetSymbolAddress((void**)&x1,    g_x1);
    cudaGetSymbolAddress((void**)&xb,    g_xb);
    cudaGetSymbolAddress((void**)&x1b,   g_x1b);
    cudaGetSymbolAddress((void**)&attnb, g_attnb);
    cudaGetSymbolAddress((void**)&wtb,   g_wtb);

    const int SMEM196 = (2 * SPAD * QRU + 64 * VTR) * (int)sizeof(uint32_t);  // 87552
    cudaFuncSetAttribute(attn196_kernel, cudaFuncAttributeMaxDynamicSharedMemorySize, SMEM196);

    dim3 tb(32, 8);
    dim3 tg_qkv(QKVW / 32, GK / 32);      // (72, 24)
    dim3 tg_out(Dd / 32, GK / 32);        // (24, 24)
    dim3 gg_qkv(QKVW / 128, NTOK / 128);  // (18, 196)
    dim3 gg_out(Dd / 128, NTOK / 128);    // (6, 196)
    int n4 = NTOK * Dd / 4;

    // x -> bf16
    f2b_kernel<<<(n4 + 255) / 256, 256>>>(x, xb, n4);
    // temporal QKV projection -> bf16 qkv
    transpose_b<<<tg_qkv, tb>>>(Wqkv_t, wtb, GK, QKVW);
    gemm_mma<<<gg_qkv, 256>>>(xb, wtb, bqkv_t, nullptr, qkvb, QKVW, 1);
    // temporal attention (S=16): warp-per-(seq,head), 18816 instances / 8 warps
    attn16_kernel<<<Bb * Pp * Hh / 8, 256>>>(qkvb, attnb);
    // temporal out-projection -> f32 y
    transpose_b<<<tg_out, tb>>>(Wo_t, wtb, GK, Dd);
    gemm_mma<<<gg_out, 256>>>(attnb, wtb, bo_t, y, nullptr, Dd, 0);
    // x1 = LN(x + y)  (+ bf16 copy)
    add_ln_kernel<<<NTOK, 256>>>(x, y, g1, b1, x1, x1b, 1);
    // spatial QKV projection -> bf16 qkv
    transpose_b<<<tg_qkv, tb>>>(Wqkv_s, wtb, GK, QKVW);
    gemm_mma<<<gg_qkv, 256>>>(x1b, wtb, bqkv_s, nullptr, qkvb, QKVW, 1);
    // spatial attention (S=196), 2 CTAs/SM
    attn196_kernel<<<dim3(Bb * Ff, Hh), 256, SMEM196>>>(qkvb, attnb);
    // spatial out-projection -> f32 y
    transpose_b<<<tg_out, tb>>>(Wo_s, wtb, GK, Dd);
    gemm_mma<<<gg_out, 256>>>(attnb, wtb, bo_s, y, nullptr, Dd, 0);
    // out = LN(x1 + y)
    add_ln_kernel<<<NTOK, 256>>>(x1, y, g2, b2, out, (__nv_bfloat16*)nullptr, 0);
}

// round 17
// speedup vs baseline: 1.4214x; 1.0132x over previous
#include <cuda_runtime.h>
#include <cuda_bf16.h>
#include <cstdint>

#define Bb 8
#define Ff 16
#define Pp 196
#define Dd 768
#define Hh 12
#define HD 64
#define NTOK (Bb*Ff*Pp)          // 25088
#define QKVW (3*Dd)              // 2304
#define GK 768                   // K for all GEMMs
#define KCHUNKS (GK/32)          // 24

// ---------------- scratch (allocation-free: __device__ globals) ----------------
__device__ __nv_bfloat16 g_qkvb[(size_t)NTOK * QKVW];  // 115 MB (bf16 qkv)
__device__ float         g_y[(size_t)NTOK * Dd];       // 77 MB
__device__ float         g_x1[(size_t)NTOK * Dd];      // 77 MB
__device__ __nv_bfloat16 g_xb[(size_t)NTOK * Dd];      // 38.5 MB
__device__ __nv_bfloat16 g_x1b[(size_t)NTOK * Dd];     // 38.5 MB
__device__ __nv_bfloat16 g_attnb[(size_t)NTOK * Dd];   // 38.5 MB
__device__ __nv_bfloat16 g_wtb[(size_t)Dd * QKVW];     // 3.5 MB

__device__ __forceinline__ void mma_bf16(float* c, const uint32_t* a, const uint32_t* b) {
    asm volatile(
        "mma.sync.aligned.m16n8k16.row.col.f32.bf16.bf16.f32 "
        "{%0,%1,%2,%3}, {%4,%5,%6,%7}, {%8,%9}, {%0,%1,%2,%3};"
        : "+f"(c[0]), "+f"(c[1]), "+f"(c[2]), "+f"(c[3])
        : "r"(a[0]), "r"(a[1]), "r"(a[2]), "r"(a[3]), "r"(b[0]), "r"(b[1]));
}
__device__ __forceinline__ void ldsm_x4(uint32_t* r, uint32_t addr) {
    asm volatile("ldmatrix.sync.aligned.m8n8.x4.shared.b16 {%0,%1,%2,%3}, [%4];"
        : "=r"(r[0]), "=r"(r[1]), "=r"(r[2]), "=r"(r[3]) : "r"(addr));
}
__device__ __forceinline__ uint32_t smem_u32(const void* p) {
    uint32_t a;
    asm("{ .reg .u64 t; cvta.to.shared.u64 t, %1; cvt.u32.u64 %0, t; }" : "=r"(a) : "l"(p));
    return a;
}
__device__ __forceinline__ void cp16(uint32_t dst, const void* src) {
    asm volatile("cp.async.cg.shared.global [%0], [%1], 16;" :: "r"(dst), "l"(src));
}
#define CP_COMMIT() asm volatile("cp.async.commit_group;" ::: "memory")
#define CP_WAIT1()  asm volatile("cp.async.wait_group 1;" ::: "memory")

__device__ __forceinline__ uint32_t packbf(float lo, float hi) {
    __nv_bfloat162 p = __float22bfloat162_rn(make_float2(lo, hi));
    return *reinterpret_cast<uint32_t*>(&p);
}

// ---------------- f32 -> bf16 convert ----------------
__global__ __launch_bounds__(256) void f2b_kernel(
    const float* __restrict__ in, __nv_bfloat16* __restrict__ out, int n4)
{
    int i = blockIdx.x * 256 + threadIdx.x;
    if (i < n4) {
        float4 v = *(const float4*)(in + (size_t)i * 4);
        uint2 u;
        u.x = packbf(v.x, v.y);
        u.y = packbf(v.z, v.w);
        *(uint2*)(out + (size_t)i * 4) = u;
    }
}

// ---------------- weight transpose to bf16: out[N,K] = bf16(in[K,N]) ----------
__global__ __launch_bounds__(256) void transpose_b(
    const float* __restrict__ in, __nv_bfloat16* __restrict__ out, int K, int N)
{
    __shared__ float t[32][33];
    int n0 = blockIdx.x * 32, k0 = blockIdx.y * 32;
    int tx = threadIdx.x, ty = threadIdx.y;   // 32 x 8
#pragma unroll
    for (int j = 0; j < 32; j += 8)
        t[ty + j][tx] = in[(size_t)(k0 + ty + j) * N + n0 + tx];
    __syncthreads();
#pragma unroll
    for (int j = 0; j < 32; j += 8)
        out[(size_t)(n0 + ty + j) * K + k0 + tx] = __float2bfloat16(t[tx][ty + j]);
}

// ---------------- BF16 mma.sync GEMM, cp.async + ldmatrix -------------------
#define ROWP32 20
#define STAGE_U (128 * ROWP32)
#define NSTG 3
__global__ __launch_bounds__(256, 2) void gemm_mma(
    const __nv_bfloat16* __restrict__ A, const __nv_bfloat16* __restrict__ Bt,
    const float* __restrict__ bias, float* __restrict__ C,
    __nv_bfloat16* __restrict__ C16, int N, int obf)
{
    __shared__ __align__(16) uint32_t As[NSTG][STAGE_U];
    __shared__ __align__(16) uint32_t Bs[NSTG][STAGE_U];

    int tid = threadIdx.x;
    int wid = tid >> 5, lane = tid & 31;
    int wr = wid >> 2, wc = wid & 3;
    int lg = lane >> 2, lk = lane & 3;
    int bm = blockIdx.y * 128, bn = blockIdx.x * 128;

    int ldr = tid >> 1;
    int half = tid & 1;
    int ebase = half * 16;
    int c2base = half * 8;

    const __nv_bfloat16* Ag = A  + (size_t)(bm + ldr) * GK + ebase;
    const __nv_bfloat16* Bg = Bt + (size_t)(bn + ldr) * GK + ebase;

    uint32_t sAs = smem_u32(&As[0][0]);
    uint32_t sBs = smem_u32(&Bs[0][0]);
    uint32_t soff = (uint32_t)(ldr * ROWP32 + c2base) * 4;

    uint32_t a_off = (uint32_t)((wr * 64 + (lane & 15)) * 80 + ((lane >> 4) & 1) * 16);
    uint32_t b_off = (uint32_t)((wc * 32 + (lane & 7) + ((lane >> 4) & 1) * 8) * 80
                                + ((lane >> 3) & 1) * 16);

    float acc[4][4][4];
#pragma unroll
    for (int i = 0; i < 4; i++)
#pragma unroll
        for (int j = 0; j < 4; j++)
#pragma unroll
            for (int k = 0; k < 4; k++) acc[i][j][k] = 0.f;

#pragma unroll
    for (int s = 0; s < 2; s++) {
        int kc = s * 32;
        uint32_t ab = sAs + s * (STAGE_U * 4) + soff;
        uint32_t bb = sBs + s * (STAGE_U * 4) + soff;
        cp16(ab,      Ag + kc);
        cp16(ab + 16, Ag + kc + 8);
        cp16(bb,      Bg + kc);
        cp16(bb + 16, Bg + kc + 8);
        CP_COMMIT();
    }

    for (int it = 0; it < KCHUNKS; it++) {
        CP_WAIT1();
        __syncthreads();
        if (it + 2 < KCHUNKS) {
            int s = (it + 2) % NSTG;
            int kc = (it + 2) * 32;
            uint32_t ab = sAs + s * (STAGE_U * 4) + soff;
            uint32_t bb = sBs + s * (STAGE_U * 4) + soff;
            cp16(ab,      Ag + kc);
            cp16(ab + 16, Ag + kc + 8);
            cp16(bb,      Bg + kc);
            cp16(bb + 16, Bg + kc + 8);
        }
        CP_COMMIT();

        uint32_t aS = sAs + (it % NSTG) * (STAGE_U * 4) + a_off;
        uint32_t bS = sBs + (it % NSTG) * (STAGE_U * 4) + b_off;
#pragma unroll
        for (int ks = 0; ks < 2; ks++) {
            uint32_t af[4][4], bf[4][2];
#pragma unroll
            for (int mt = 0; mt < 4; mt++)
                ldsm_x4(af[mt], aS + mt * (16 * 80) + ks * 32);
#pragma unroll
            for (int j = 0; j < 2; j++)
                ldsm_x4(&bf[2 * j][0], bS + j * (16 * 80) + ks * 32);
#pragma unroll
            for (int mt = 0; mt < 4; mt++)
#pragma unroll
                for (int nt = 0; nt < 4; nt++)
                    mma_bf16(acc[mt][nt], af[mt], bf[nt]);
        }
    }

#pragma unroll
    for (int mt = 0; mt < 4; mt++) {
        size_t r0 = (size_t)(bm + wr * 64 + mt * 16 + lg);
#pragma unroll
        for (int nt = 0; nt < 4; nt++) {
            int c0 = bn + wc * 32 + nt * 8 + lk * 2;
            float bx = bias[c0], by = bias[c0 + 1];
            float v00 = acc[mt][nt][0] + bx, v01 = acc[mt][nt][1] + by;
            float v10 = acc[mt][nt][2] + bx, v11 = acc[mt][nt][3] + by;
            if (obf) {
                *(uint32_t*)(C16 + r0 * N + c0)       = packbf(v00, v01);
                *(uint32_t*)(C16 + (r0 + 8) * N + c0) = packbf(v10, v11);
            } else {
                *(float2*)(C + r0 * N + c0)       = make_float2(v00, v01);
                *(float2*)(C + (r0 + 8) * N + c0) = make_float2(v10, v11);
            }
        }
    }
}

// ---------------- temporal attention, S=16: warp-per-(seq,head), MMA, no smem
__global__ __launch_bounds__(256) void attn16_kernel(
    const __nv_bfloat16* __restrict__ qkv, __nv_bfloat16* __restrict__ out)
{
    int wid = threadIdx.x >> 5, lane = threadIdx.x & 31;
    int lg = lane >> 2, lk = lane & 3;
    int inst = blockIdx.x * 8 + wid;          // 0 .. 18815
    int h = inst % Hh;
    int seq = inst / Hh;
    int b = seq / Pp, p = seq % Pp;
    int base = b * Ff * Pp + p;               // + f*Pp per frame

    const uint16_t* qk = (const uint16_t*)qkv;
    const size_t RSTRIDE = (size_t)Pp * QKVW; // stride between frames

    uint32_t qa[4][4];
    {
        size_t r0 = (size_t)(base + lg * Pp) * QKVW + h * HD;
        size_t r1 = r0 + 8 * RSTRIDE;
#pragma unroll
        for (int kc = 0; kc < 4; kc++) {
            int k0 = kc * 16 + lk * 2;
            qa[kc][0] = *(const uint32_t*)(qk + r0 + k0);
            qa[kc][1] = *(const uint32_t*)(qk + r1 + k0);
            qa[kc][2] = *(const uint32_t*)(qk + r0 + k0 + 8);
            qa[kc][3] = *(const uint32_t*)(qk + r1 + k0 + 8);
        }
    }

    float sc[2][4];
    sc[0][0] = sc[0][1] = sc[0][2] = sc[0][3] = 0.f;
    sc[1][0] = sc[1][1] = sc[1][2] = sc[1][3] = 0.f;
#pragma unroll
    for (int nt = 0; nt < 2; nt++) {
        size_t kr = (size_t)(base + (nt * 8 + lg) * Pp) * QKVW + Dd + h * HD;
#pragma unroll
        for (int kc = 0; kc < 4; kc++) {
            int k0 = kc * 16 + lk * 2;
            uint32_t bfr[2];
            bfr[0] = *(const uint32_t*)(qk + kr + k0);
            bfr[1] = *(const uint32_t*)(qk + kr + k0 + 8);
            mma_bf16(sc[nt], qa[kc], bfr);
        }
    }
#pragma unroll
    for (int nt = 0; nt < 2; nt++) {
        sc[nt][0] *= 0.125f; sc[nt][1] *= 0.125f;
        sc[nt][2] *= 0.125f; sc[nt][3] *= 0.125f;
    }

    float m0 = fmaxf(fmaxf(sc[0][0], sc[0][1]), fmaxf(sc[1][0], sc[1][1]));
    float m1 = fmaxf(fmaxf(sc[0][2], sc[0][3]), fmaxf(sc[1][2], sc[1][3]));
    m0 = fmaxf(m0, __shfl_xor_sync(0xffffffffu, m0, 1));
    m0 = fmaxf(m0, __shfl_xor_sync(0xffffffffu, m0, 2));
    m1 = fmaxf(m1, __shfl_xor_sync(0xffffffffu, m1, 1));
    m1 = fmaxf(m1, __shfl_xor_sync(0xffffffffu, m1, 2));
    float s0 = 0.f, s1 = 0.f;
#pragma unroll
    for (int nt = 0; nt < 2; nt++) {
        sc[nt][0] = __expf(sc[nt][0] - m0); s0 += sc[nt][0];
        sc[nt][1] = __expf(sc[nt][1] - m0); s0 += sc[nt][1];
        sc[nt][2] = __expf(sc[nt][2] - m1); s1 += sc[nt][2];
        sc[nt][3] = __expf(sc[nt][3] - m1); s1 += sc[nt][3];
    }
    s0 += __shfl_xor_sync(0xffffffffu, s0, 1);
    s0 += __shfl_xor_sync(0xffffffffu, s0, 2);
    s1 += __shfl_xor_sync(0xffffffffu, s1, 1);
    s1 += __shfl_xor_sync(0xffffffffu, s1, 2);

    uint32_t pa[4];
    pa[0] = packbf(sc[0][0], sc[0][1]);
    pa[1] = packbf(sc[0][2], sc[0][3]);
    pa[2] = packbf(sc[1][0], sc[1][1]);
    pa[3] = packbf(sc[1][2], sc[1][3]);

    size_t v0r = (size_t)(base + (2 * lk) * Pp)     * QKVW + 2 * Dd + h * HD;
    size_t v1r = v0r + RSTRIDE;
    size_t v2r = v0r + 8 * RSTRIDE;
    size_t v3r = v0r + 9 * RSTRIDE;

    float oa[8][4];
#pragma unroll
    for (int nd = 0; nd < 8; nd++)
        oa[nd][0] = oa[nd][1] = oa[nd][2] = oa[nd][3] = 0.f;
#pragma unroll
    for (int nd = 0; nd < 8; nd++) {
        int n = nd * 8 + lg;
        uint32_t bb[2];
        bb[0] = (uint32_t)qk[v0r + n] | ((uint32_t)qk[v1r + n] << 16);
        bb[1] = (uint32_t)qk[v2r + n] | ((uint32_t)qk[v3r + n] << 16);
        mma_bf16(oa[nd], pa, bb);
    }

    float inv0 = 1.0f / s0, inv1 = 1.0f / s1;
    size_t o0 = (size_t)(base + lg * Pp) * Dd + h * HD;
    size_t o1 = (size_t)(base + (lg + 8) * Pp) * Dd + h * HD;
#pragma unroll
    for (int nd = 0; nd < 8; nd++) {
        int col = nd * 8 + lk * 2;
        *(uint32_t*)(out + o0 + col) = packbf(oa[nd][0] * inv0, oa[nd][1] * inv0);
        *(uint32_t*)(out + o1 + col) = packbf(oa[nd][2] * inv1, oa[nd][3] * inv1);
    }
}

// ---------------- spatial attention, S=196 padded to 208, bf16 MMA ----------
#define SPAD 208
#define QRU 36
#define VTR 108
__global__ __launch_bounds__(256, 2) void attn196_kernel(
    const __nv_bfloat16* __restrict__ qkv, __nv_bfloat16* __restrict__ out)
{
    extern __shared__ __align__(16) uint32_t sm196[];
    uint32_t* Qu = sm196;                 // [208][36]
    uint32_t* Ku = Qu + SPAD * QRU;       // [208][36]
    uint32_t* Tu = Ku + SPAD * QRU;       // Vt: [64][108]

    int h = blockIdx.y;
    int base = blockIdx.x * Pp;
    int tid = threadIdx.x;
    int wid = tid >> 5, lane = tid & 31;
    int lg = lane >> 2, lk = lane & 3;

    const uint16_t* qkvu = (const uint16_t*)qkv;

    for (int i = tid; i < SPAD * 16; i += 256) {
        int s = i >> 4, d4 = (i & 15) * 2;
        uint32_t q0 = 0, q1 = 0, k0 = 0, k1 = 0;
        if (s < Pp) {
            const __nv_bfloat16* row = qkv + (size_t)(base + s) * QKVW + h * HD + d4 * 2;
            uint2 qq = *(const uint2*)(row);
            uint2 kk = *(const uint2*)(row + Dd);
            q0 = qq.x; q1 = qq.y;
            k0 = kk.x; k1 = kk.y;
        }
        Qu[s * QRU + d4] = q0; Qu[s * QRU + d4 + 1] = q1;
        Ku[s * QRU + d4] = k0; Ku[s * QRU + d4 + 1] = k1;
    }
    for (int i = tid; i < 64 * 104; i += 256) {
        int d = i & 63, s2 = i >> 6;
        int r0 = 2 * s2, r1 = 2 * s2 + 1;
        uint32_t lo = 0, hi = 0;
        if (r0 < Pp)
            lo = qkvu[(size_t)(base + r0) * QKVW + 2 * Dd + h * HD + d];
        if (r1 < Pp)
            hi = qkvu[(size_t)(base + r1) * QKVW + 2 * Dd + h * HD + d];
        Tu[d * VTR + s2] = lo | (hi << 16);
    }
    __syncthreads();

    for (int mt = wid; mt < 13; mt += 8) {
        int r = mt * 16 + lg;

        uint32_t qa[4][4];
#pragma unroll
        for (int kc = 0; kc < 4; kc++) {
            int c2 = kc * 8 + lk;
            qa[kc][0] = Qu[r * QRU + c2];
            qa[kc][1] = Qu[(r + 8) * QRU + c2];
            qa[kc][2] = Qu[r * QRU + c2 + 4];
            qa[kc][3] = Qu[(r + 8) * QRU + c2 + 4];
        }

        float sc[26][4];
#pragma unroll
        for (int nt = 0; nt < 26; nt++)
            sc[nt][0] = sc[nt][1] = sc[nt][2] = sc[nt][3] = 0.f;
#pragma unroll
        for (int nt = 0; nt < 26; nt++) {
            int n = nt * 8 + lg;
#pragma unroll
            for (int kc = 0; kc < 4; kc++) {
                uint32_t b[2];
                b[0] = Ku[n * QRU + kc * 8 + lk];
                b[1] = Ku[n * QRU + kc * 8 + lk + 4];
                mma_bf16(sc[nt], qa[kc], b);
            }
        }

#pragma unroll
        for (int nt = 0; nt < 26; nt++) {
            int col0 = nt * 8 + 2 * lk;
            sc[nt][0] = (col0     < Pp) ? sc[nt][0] * 0.125f : -1e30f;
            sc[nt][1] = (col0 + 1 < Pp) ? sc[nt][1] * 0.125f : -1e30f;
            sc[nt][2] = (col0     < Pp) ? sc[nt][2] * 0.125f : -1e30f;
            sc[nt][3] = (col0 + 1 < Pp) ? sc[nt][3] * 0.125f : -1e30f;
        }

        float m0 = -1e30f, m1 = -1e30f;
#pragma unroll
        for (int nt = 0; nt < 26; nt++) {
            m0 = fmaxf(m0, fmaxf(sc[nt][0], sc[nt][1]));
            m1 = fmaxf(m1, fmaxf(sc[nt][2], sc[nt][3]));
        }
        m0 = fmaxf(m0, __shfl_xor_sync(0xffffffffu, m0, 1));
        m0 = fmaxf(m0, __shfl_xor_sync(0xffffffffu, m0, 2));
        m1 = fmaxf(m1, __shfl_xor_sync(0xffffffffu, m1, 1));
        m1 = fmaxf(m1, __shfl_xor_sync(0xffffffffu, m1, 2));

        float s0 = 0.f, s1 = 0.f;
#pragma unroll
        for (int nt = 0; nt < 26; nt++) {
            sc[nt][0] = __expf(sc[nt][0] - m0); s0 += sc[nt][0];
            sc[nt][1] = __expf(sc[nt][1] - m0); s0 += sc[nt][1];
            sc[nt][2] = __expf(sc[nt][2] - m1); s1 += sc[nt][2];
            sc[nt][3] = __expf(sc[nt][3] - m1); s1 += sc[nt][3];
        }
        s0 += __shfl_xor_sync(0xffffffffu, s0, 1);
        s0 += __shfl_xor_sync(0xffffffffu, s0, 2);
        s1 += __shfl_xor_sync(0xffffffffu, s1, 1);
        s1 += __shfl_xor_sync(0xffffffffu, s1, 2);

        uint32_t pk[13][4];
#pragma unroll
        for (int j = 0; j < 13; j++) {
            pk[j][0] = packbf(sc[2 * j][0],     sc[2 * j][1]);
            pk[j][1] = packbf(sc[2 * j][2],     sc[2 * j][3]);
            pk[j][2] = packbf(sc[2 * j + 1][0], sc[2 * j + 1][1]);
            pk[j][3] = packbf(sc[2 * j + 1][2], sc[2 * j + 1][3]);
        }

        float oa[8][4];
#pragma unroll
        for (int nd = 0; nd < 8; nd++)
            oa[nd][0] = oa[nd][1] = oa[nd][2] = oa[nd][3] = 0.f;
#pragma unroll
        for (int j = 0; j < 13; j++) {
#pragma unroll
            for (int nd = 0; nd < 8; nd++) {
                int n = nd * 8 + lg;
                uint32_t b[2];
                b[0] = Tu[n * VTR + j * 8 + lk];
                b[1] = Tu[n * VTR + j * 8 + lk + 4];
                mma_bf16(oa[nd], pk[j], b);
            }
        }

        float inv0 = 1.0f / s0, inv1 = 1.0f / s1;
        int row0 = r, row1 = r + 8;
#pragma unroll
        for (int nd = 0; nd < 8; nd++) {
            int col = nd * 8 + 2 * lk;
            if (row0 < Pp) {
                uint32_t u = packbf(oa[nd][0] * inv0, oa[nd][1] * inv0);
                *(uint32_t*)(out + (size_t)(base + row0) * Dd + h * HD + col) = u;
            }
            if (row1 < Pp) {
                uint32_t u = packbf(oa[nd][2] * inv1, oa[nd][3] * inv1);
                *(uint32_t*)(out + (size_t)(base + row1) * Dd + h * HD + col) = u;
            }
        }
    }
}

// ---------------- fused residual + LayerNorm (float4, 192 threads) ----------
__global__ __launch_bounds__(192) void add_ln_kernel(
    const float* __restrict__ x, const float* __restrict__ y,
    const float* __restrict__ g, const float* __restrict__ b,
    float* __restrict__ out, __nv_bfloat16* __restrict__ outb, int wb)
{
    __shared__ float ps[6], ps2[6];
    __shared__ float red[2];

    size_t row = blockIdx.x;
    int tid = threadIdx.x;
    int lane = tid & 31, wid = tid >> 5;
    int d = tid * 4;

    float4 xv = *(const float4*)(x + row * Dd + d);
    float4 yv = *(const float4*)(y + row * Dd + d);
    float4 v = make_float4(xv.x + yv.x, xv.y + yv.y, xv.z + yv.z, xv.w + yv.w);

    float s  = v.x + v.y + v.z + v.w;
    float s2 = v.x * v.x + v.y * v.y + v.z * v.z + v.w * v.w;
#pragma unroll
    for (int o = 16; o; o >>= 1) {
        s  += __shfl_xor_sync(0xffffffffu, s, o);
        s2 += __shfl_xor_sync(0xffffffffu, s2, o);
    }
    if (lane == 0) { ps[wid] = s; ps2[wid] = s2; }
    __syncthreads();
    if (tid == 0) {
        s = ps[0]; s2 = ps2[0];
#pragma unroll
        for (int w = 1; w < 6; w++) { s += ps[w]; s2 += ps2[w]; }
        float mean = s / Dd;
        float var = s2 / Dd - mean * mean;
        red[0] = mean;
        red[1] = rsqrtf(var + 1e-5f);
    }
    __syncthreads();
    float mean = red[0], rstd = red[1];

    float4 gv = *(const float4*)(g + d);
    float4 bv = *(const float4*)(b + d);
    float4 o;
    o.x = (v.x - mean) * rstd * gv.x + bv.x;
    o.y = (v.y - mean) * rstd * gv.y + bv.y;
    o.z = (v.z - mean) * rstd * gv.z + bv.z;
    o.w = (v.w - mean) * rstd * gv.w + bv.w;
    *(float4*)(out + row * Dd + d) = o;
    if (wb) {
        uint2 u;
        u.x = packbf(o.x, o.y);
        u.y = packbf(o.z, o.w);
        *(uint2*)(outb + row * Dd + d) = u;
    }
}

// ---------------- launch ----------------
extern "C" void kernel_launch(void* const* d_in, const int* in_sizes, int n_in,
                              void* d_out, int out_size)
{
    const float* x      = (const float*)d_in[0];
    const float* Wqkv_t = (const float*)d_in[1];
    const float* bqkv_t = (const float*)d_in[2];
    const float* Wo_t   = (const float*)d_in[3];
    const float* bo_t   = (const float*)d_in[4];
    const float* Wqkv_s = (const float*)d_in[5];
    const float* bqkv_s = (const float*)d_in[6];
    const float* Wo_s   = (const float*)d_in[7];
    const float* bo_s   = (const float*)d_in[8];
    const float* g1     = (const float*)d_in[9];
    const float* b1     = (const float*)d_in[10];
    const float* g2     = (const float*)d_in[11];
    const float* b2     = (const float*)d_in[12];
    float* out = (float*)d_out;

    float *y, *x1;
    __nv_bfloat16 *qkvb, *xb, *x1b, *attnb, *wtb;
    cudaGetSymbolAddress((void**)&qkvb,  g_qkvb);
    cudaGetSymbolAddress((void**)&y,     g_y);
    cudaGetSymbolAddress((void**)&x1,    g_x1);
    cudaGetSymbolAddress((void**)&xb,    g_xb);
    cudaGetSymbolAddress((void**)&x1b,   g_x1b);
    cudaGetSymbolAddress((void**)&attnb, g_attnb);
    cudaGetSymbolAddress((void**)&wtb,   g_wtb);

    const int SMEM196 = (2 * SPAD * QRU + 64 * VTR) * (int)sizeof(uint32_t);  // 87552
    cudaFuncSetAttribute(attn196_kernel, cudaFuncAttributeMaxDynamicSharedMemorySize, SMEM196);

    dim3 tb(32, 8);
    dim3 tg_qkv(QKVW / 32, GK / 32);      // (72, 24)
    dim3 tg_out(Dd / 32, GK / 32);        // (24, 24)
    dim3 gg_qkv(QKVW / 128, NTOK / 128);  // (18, 196)
    dim3 gg_out(Dd / 128, NTOK / 128);    // (6, 196)
    int n4 = NTOK * Dd / 4;

    // x -> bf16
    f2b_kernel<<<(n4 + 255) / 256, 256>>>(x, xb, n4);
    // temporal QKV projection -> bf16 qkv
    transpose_b<<<tg_qkv, tb>>>(Wqkv_t, wtb, GK, QKVW);
    gemm_mma<<<gg_qkv, 256>>>(xb, wtb, bqkv_t, nullptr, qkvb, QKVW, 1);
    // temporal attention (S=16): warp-per-(seq,head)
    attn16_kernel<<<Bb * Pp * Hh / 8, 256>>>(qkvb, attnb);
    // temporal out-projection -> f32 y
    transpose_b<<<tg_out, tb>>>(Wo_t, wtb, GK, Dd);
    gemm_mma<<<gg_out, 256>>>(attnb, wtb, bo_t, y, nullptr, Dd, 0);
    // x1 = LN(x + y)  (+ bf16 copy)
    add_ln_kernel<<<NTOK, 192>>>(x, y, g1, b1, x1, x1b, 1);
    // spatial QKV projection -> bf16 qkv
    transpose_b<<<tg_qkv, tb>>>(Wqkv_s, wtb, GK, QKVW);
    gemm_mma<<<gg_qkv, 256>>>(x1b, wtb, bqkv_s, nullptr, qkvb, QKVW, 1);
    // spatial attention (S=196), 2 CTAs/SM
    attn196_kernel<<<dim3(Bb * Ff, Hh), 256, SMEM196>>>(qkvb, attnb);
    // spatial out-projection -> f32 y
    transpose_b<<<tg_out, tb>>>(Wo_s, wtb, GK, Dd);
    gemm_mma<<<gg_out, 256>>>(attnb, wtb, bo_s, y, nullptr, Dd, 0);
    // out = LN(x1 + y)
    add_ln_kernel<<<NTOK, 192>>>(x1, y, g2, b2, out, (__nv_bfloat16*)nullptr, 0);
}